// round 1
// baseline (speedup 1.0000x reference)
#include <cuda_runtime.h>

// Problem constants (fixed by the reference)
#define Cdim 2048
#define Sdim 2048
#define Bdim 4
#define Hdim 16
#define Ddim 128
#define Mtok (Bdim * Sdim)          // 8192 tokens

// Scratch (device globals — no allocation allowed in kernel_launch)
__device__ float g_qkv[(size_t)Mtok * 3 * Cdim];   // [B*S, 3C]  (201 MB)
__device__ float g_y[(size_t)Mtok * Cdim];         // [B*S, C]   (64 MB)

// ---------------------------------------------------------------------------
// GEMM: C[M,N] = A[M,K] @ B[K,N] + bias[N]
// 128x128x16 tile, 256 threads, 8x8 micro-tile per thread (split 2x 4-wide).
// ---------------------------------------------------------------------------
__global__ __launch_bounds__(256) void gemm_bias_kernel(
    const float* __restrict__ A, const float* __restrict__ B,
    const float* __restrict__ bias, float* __restrict__ Cmat,
    int M, int N, int K)
{
    __shared__ float As[16][132];   // A transposed [k][m], pad 4 to break conflicts
    __shared__ float Bs[16][128];   // B direct [k][n]

    const int t  = threadIdx.x;
    const int tx = t & 15;
    const int ty = t >> 4;
    const int m0 = blockIdx.y * 128;
    const int n0 = blockIdx.x * 128;

    float acc[8][8];
#pragma unroll
    for (int i = 0; i < 8; ++i)
#pragma unroll
        for (int j = 0; j < 8; ++j) acc[i][j] = 0.f;

    const int ra = t >> 2;          // 0..63 (A tile row, + 64 second half)
    const int ca = (t & 3) * 4;     // k sub-col (float4)
    const int kb = t >> 5;          // 0..7  (B tile k row, + 8 second half)
    const int cb = (t & 31) * 4;    // n col (float4)

    for (int k0 = 0; k0 < K; k0 += 16) {
#pragma unroll
        for (int h = 0; h < 2; ++h) {
            int rr = ra + h * 64;
            float4 av = *(const float4*)(A + (size_t)(m0 + rr) * K + k0 + ca);
            As[ca + 0][rr] = av.x;
            As[ca + 1][rr] = av.y;
            As[ca + 2][rr] = av.z;
            As[ca + 3][rr] = av.w;
        }
#pragma unroll
        for (int h = 0; h < 2; ++h) {
            *(float4*)(&Bs[kb + h * 8][cb]) =
                *(const float4*)(B + (size_t)(k0 + kb + h * 8) * N + n0 + cb);
        }
        __syncthreads();

#pragma unroll
        for (int k = 0; k < 16; ++k) {
            float4 a0 = *(const float4*)(&As[k][ty * 4]);
            float4 a1 = *(const float4*)(&As[k][64 + ty * 4]);
            float4 b0 = *(const float4*)(&Bs[k][tx * 4]);
            float4 b1 = *(const float4*)(&Bs[k][64 + tx * 4]);
            float a[8] = {a0.x, a0.y, a0.z, a0.w, a1.x, a1.y, a1.z, a1.w};
            float b[8] = {b0.x, b0.y, b0.z, b0.w, b1.x, b1.y, b1.z, b1.w};
#pragma unroll
            for (int i = 0; i < 8; ++i)
#pragma unroll
                for (int j = 0; j < 8; ++j)
                    acc[i][j] = fmaf(a[i], b[j], acc[i][j]);
        }
        __syncthreads();
    }

    float4 bv0 = *(const float4*)(bias + n0 + tx * 4);
    float4 bv1 = *(const float4*)(bias + n0 + 64 + tx * 4);
    float bb[8] = {bv0.x, bv0.y, bv0.z, bv0.w, bv1.x, bv1.y, bv1.z, bv1.w};
#pragma unroll
    for (int i = 0; i < 8; ++i) {
        int m = m0 + ((i < 4) ? (ty * 4 + i) : (64 + ty * 4 + (i - 4)));
        float* crow = Cmat + (size_t)m * N + n0;
        *(float4*)(crow + tx * 4) = make_float4(
            acc[i][0] + bb[0], acc[i][1] + bb[1], acc[i][2] + bb[2], acc[i][3] + bb[3]);
        *(float4*)(crow + 64 + tx * 4) = make_float4(
            acc[i][4] + bb[4], acc[i][5] + bb[5], acc[i][6] + bb[6], acc[i][7] + bb[7]);
    }
}

// ---------------------------------------------------------------------------
// Flash attention (causal), fp32. One block = one (b, h, 64-row q-tile).
// 256 threads as 16x16; S micro-tile 4x4 per thread; O micro-tile 4x8.
// Q/K stored d-major (transposed) in smem for GEMM-style access; V direct.
// ---------------------------------------------------------------------------
#define QT_PITCH 68                       // 64 rows + pad 4
#define ATTN_SMEM_FLOATS (128 * QT_PITCH * 2 + 64 * 128 + 64 * QT_PITCH)

__global__ __launch_bounds__(256) void attn_kernel()
{
    extern __shared__ float sm[];
    float* Qt = sm;                        // [128][68]  (d-major)
    float* Kt = Qt + 128 * QT_PITCH;       // [128][68]  (d-major)
    float* Vs = Kt + 128 * QT_PITCH;       // [64][128]
    float* Ps = Vs + 64 * 128;             // [64][68]

    const int t  = threadIdx.x;
    const int tx = t & 15;
    const int ty = t >> 4;
    const int qt = blockIdx.x;             // 0..31
    const int h  = blockIdx.y;             // 0..15
    const int b  = blockIdx.z;             // 0..3

    const size_t rstride = 3 * Cdim;
    const float* qbase = g_qkv + (size_t)b * Sdim * rstride + (size_t)h * Ddim;
    const float* kbase = qbase + Cdim;
    const float* vbase = qbase + 2 * Cdim;
    const int m0 = qt * 64;

    // Load Q tile transposed: Qt[d][row]
    {
        const int r  = t >> 2;
        const int c4 = (t & 3) * 4;
#pragma unroll
        for (int i = 0; i < 8; ++i) {
            int d = c4 + i * 16;
            float4 qv = *(const float4*)(qbase + (size_t)(m0 + r) * rstride + d);
            Qt[(d + 0) * QT_PITCH + r] = qv.x;
            Qt[(d + 1) * QT_PITCH + r] = qv.y;
            Qt[(d + 2) * QT_PITCH + r] = qv.z;
            Qt[(d + 3) * QT_PITCH + r] = qv.w;
        }
    }

    float m_i[4], l_i[4], o[4][8];
#pragma unroll
    for (int i = 0; i < 4; ++i) {
        m_i[i] = -1e30f;
        l_i[i] = 0.f;
#pragma unroll
        for (int j = 0; j < 8; ++j) o[i][j] = 0.f;
    }

    const float scale = 0.08838834764831845f;  // 1/sqrt(128)

    for (int kt = 0; kt <= qt; ++kt) {
        const int n0 = kt * 64;
        __syncthreads();   // protect Kt/Vs/Ps (and Qt on first iter) from prior phase

        // Load K tile transposed + V tile direct
        {
            const int r  = t >> 2;
            const int c4 = (t & 3) * 4;
#pragma unroll
            for (int i = 0; i < 8; ++i) {
                int d = c4 + i * 16;
                float4 kv = *(const float4*)(kbase + (size_t)(n0 + r) * rstride + d);
                Kt[(d + 0) * QT_PITCH + r] = kv.x;
                Kt[(d + 1) * QT_PITCH + r] = kv.y;
                Kt[(d + 2) * QT_PITCH + r] = kv.z;
                Kt[(d + 3) * QT_PITCH + r] = kv.w;
            }
#pragma unroll
            for (int i = 0; i < 8; ++i) {
                int idx = t + i * 256;
                int r2 = idx >> 5;
                int c  = (idx & 31) * 4;
                *(float4*)(&Vs[r2 * 128 + c]) =
                    *(const float4*)(vbase + (size_t)(n0 + r2) * rstride + c);
            }
        }
        __syncthreads();

        // S = (Q K^T) * scale, 4x4 per thread
        float s[4][4];
#pragma unroll
        for (int i = 0; i < 4; ++i)
#pragma unroll
            for (int j = 0; j < 4; ++j) s[i][j] = 0.f;

#pragma unroll 4
        for (int d = 0; d < 128; ++d) {
            float4 qa = *(const float4*)(&Qt[d * QT_PITCH + ty * 4]);
            float4 kb4 = *(const float4*)(&Kt[d * QT_PITCH + tx * 4]);
            float a[4] = {qa.x, qa.y, qa.z, qa.w};
            float bb[4] = {kb4.x, kb4.y, kb4.z, kb4.w};
#pragma unroll
            for (int i = 0; i < 4; ++i)
#pragma unroll
                for (int j = 0; j < 4; ++j)
                    s[i][j] = fmaf(a[i], bb[j], s[i][j]);
        }

        const bool diag = (kt == qt);
#pragma unroll
        for (int i = 0; i < 4; ++i) {
            int qrow = m0 + ty * 4 + i;
#pragma unroll
            for (int j = 0; j < 4; ++j) {
                s[i][j] *= scale;
                int kcol = n0 + tx * 4 + j;
                if (diag && kcol > qrow) s[i][j] = -1e30f;
            }
        }

        // Online softmax per row (row is spread over 16 consecutive lanes)
#pragma unroll
        for (int i = 0; i < 4; ++i) {
            float mx = fmaxf(fmaxf(s[i][0], s[i][1]), fmaxf(s[i][2], s[i][3]));
#pragma unroll
            for (int w = 8; w >= 1; w >>= 1)
                mx = fmaxf(mx, __shfl_xor_sync(0xffffffffu, mx, w));
            float m_new = fmaxf(m_i[i], mx);
            float alpha = __expf(m_i[i] - m_new);
            float sum = 0.f;
#pragma unroll
            for (int j = 0; j < 4; ++j) {
                float p = __expf(s[i][j] - m_new);
                s[i][j] = p;
                sum += p;
            }
#pragma unroll
            for (int w = 8; w >= 1; w >>= 1)
                sum += __shfl_xor_sync(0xffffffffu, sum, w);
            l_i[i] = l_i[i] * alpha + sum;
            m_i[i] = m_new;
#pragma unroll
            for (int c = 0; c < 8; ++c) o[i][c] *= alpha;
#pragma unroll
            for (int j = 0; j < 4; ++j)
                Ps[(ty * 4 + i) * QT_PITCH + tx * 4 + j] = s[i][j];
        }
        __syncthreads();

        // O += P @ V   (4 rows x 8 cols per thread; cols tx*4 and 64+tx*4)
#pragma unroll 2
        for (int j = 0; j < 64; ++j) {
            float p[4];
#pragma unroll
            for (int i = 0; i < 4; ++i)
                p[i] = Ps[(ty * 4 + i) * QT_PITCH + j];
            float4 v0 = *(const float4*)(&Vs[j * 128 + tx * 4]);
            float4 v1 = *(const float4*)(&Vs[j * 128 + 64 + tx * 4]);
            float v[8] = {v0.x, v0.y, v0.z, v0.w, v1.x, v1.y, v1.z, v1.w};
#pragma unroll
            for (int i = 0; i < 4; ++i)
#pragma unroll
                for (int c = 0; c < 8; ++c)
                    o[i][c] = fmaf(p[i], v[c], o[i][c]);
        }
    }

    // Normalize and write y[b, row, h*D + c]
    float* ybase = g_y + (size_t)b * Sdim * Cdim + (size_t)h * Ddim;
#pragma unroll
    for (int i = 0; i < 4; ++i) {
        float inv = 1.0f / l_i[i];
        size_t rowoff = (size_t)(m0 + ty * 4 + i) * Cdim;
        *(float4*)(ybase + rowoff + tx * 4) =
            make_float4(o[i][0] * inv, o[i][1] * inv, o[i][2] * inv, o[i][3] * inv);
        *(float4*)(ybase + rowoff + 64 + tx * 4) =
            make_float4(o[i][4] * inv, o[i][5] * inv, o[i][6] * inv, o[i][7] * inv);
    }
}

// ---------------------------------------------------------------------------
// Launch
// ---------------------------------------------------------------------------
extern "C" void kernel_launch(void* const* d_in, const int* in_sizes, int n_in,
                              void* d_out, int out_size)
{
    const float* x      = (const float*)d_in[0];
    const float* w_qkv  = (const float*)d_in[1];
    const float* b_qkv  = (const float*)d_in[2];
    const float* w_proj = (const float*)d_in[3];
    const float* b_proj = (const float*)d_in[4];
    float* out = (float*)d_out;

    float* qkv = nullptr;
    float* y   = nullptr;
    cudaGetSymbolAddress((void**)&qkv, g_qkv);
    cudaGetSymbolAddress((void**)&y, g_y);

    // 1) qkv = x @ w_qkv + b_qkv      [8192, 6144]
    {
        dim3 grid(3 * Cdim / 128, Mtok / 128);
        gemm_bias_kernel<<<grid, 256>>>(x, w_qkv, b_qkv, qkv, Mtok, 3 * Cdim, Cdim);
    }

    // 2) flash attention -> y          [8192, 2048]
    {
        size_t smem = ATTN_SMEM_FLOATS * sizeof(float);   // ~117 KB
        cudaFuncSetAttribute(attn_kernel,
                             cudaFuncAttributeMaxDynamicSharedMemorySize, (int)smem);
        dim3 grid(Sdim / 64, Hdim, Bdim);
        attn_kernel<<<grid, 256, smem>>>();
    }

    // 3) out = y @ w_proj + b_proj     [8192, 2048]
    {
        dim3 grid(Cdim / 128, Mtok / 128);
        gemm_bias_kernel<<<grid, 256>>>(y, w_proj, b_proj, out, Mtok, Cdim, Cdim);
    }
}

// round 3
// speedup vs baseline: 1.6277x; 1.6277x over previous
#include <cuda_runtime.h>
#include <cuda_bf16.h>
#include <cstdint>

// Problem constants
#define Cdim 2048
#define Sdim 2048
#define Bdim 4
#define Hdim 16
#define Ddim 128
#define Mtok (Bdim * Sdim)          // 8192

// ---------------------------------------------------------------------------
// Scratch (device globals — no allocation allowed)
// ---------------------------------------------------------------------------
__device__ float g_qkv[(size_t)Mtok * 3 * Cdim];            // [8192, 6144] fp32
__device__ float g_y[(size_t)Mtok * Cdim];                  // [8192, 2048] fp32
__device__ __nv_bfloat16 g_xh[(size_t)Mtok * Cdim];
__device__ __nv_bfloat16 g_xl[(size_t)Mtok * Cdim];
__device__ __nv_bfloat16 g_yh[(size_t)Mtok * Cdim];
__device__ __nv_bfloat16 g_yl[(size_t)Mtok * Cdim];
__device__ __nv_bfloat16 g_wqkvT_h[(size_t)3 * Cdim * Cdim];  // [6144, 2048] (N,K)
__device__ __nv_bfloat16 g_wqkvT_l[(size_t)3 * Cdim * Cdim];
__device__ __nv_bfloat16 g_wprojT_h[(size_t)Cdim * Cdim];     // [2048, 2048]
__device__ __nv_bfloat16 g_wprojT_l[(size_t)Cdim * Cdim];

// ---------------------------------------------------------------------------
// PTX helpers (base-ISA only: cp.async / ldmatrix / mma.sync — NO tcgen05)
// ---------------------------------------------------------------------------
__device__ __forceinline__ uint32_t smem_u32(const void* p) {
    uint32_t a;
    asm("{ .reg .u64 t; cvta.to.shared.u64 t, %1; cvt.u32.u64 %0, t; }" : "=r"(a) : "l"(p));
    return a;
}

#define CP_ASYNC16(dst, src) \
    asm volatile("cp.async.cg.shared.global [%0], [%1], 16;" :: "r"(dst), "l"(src))
#define CP_COMMIT() asm volatile("cp.async.commit_group;" ::: "memory")
#define CP_WAIT(n)  asm volatile("cp.async.wait_group %0;" :: "n"(n) : "memory")

__device__ __forceinline__ void ldsm4(uint32_t* r, uint32_t addr) {
    asm volatile("ldmatrix.sync.aligned.m8n8.x4.shared.b16 {%0,%1,%2,%3}, [%4];"
                 : "=r"(r[0]), "=r"(r[1]), "=r"(r[2]), "=r"(r[3]) : "r"(addr));
}

__device__ __forceinline__ void mma16816(float* d, const uint32_t* a,
                                         uint32_t b0, uint32_t b1) {
    asm volatile(
        "mma.sync.aligned.m16n8k16.row.col.f32.bf16.bf16.f32 "
        "{%0,%1,%2,%3}, {%4,%5,%6,%7}, {%8,%9}, {%0,%1,%2,%3};"
        : "+f"(d[0]), "+f"(d[1]), "+f"(d[2]), "+f"(d[3])
        : "r"(a[0]), "r"(a[1]), "r"(a[2]), "r"(a[3]), "r"(b0), "r"(b1));
}

// ---------------------------------------------------------------------------
// Conversion kernels (fp32 -> bf16 hi/lo split)
// ---------------------------------------------------------------------------
__global__ void split_kernel(const float* __restrict__ in,
                             __nv_bfloat16* __restrict__ hi,
                             __nv_bfloat16* __restrict__ lo, int n)
{
    int i = (blockIdx.x * blockDim.x + threadIdx.x) * 4;
    if (i >= n) return;
    float4 v = *(const float4*)(in + i);
    float vv[4] = {v.x, v.y, v.z, v.w};
    __nv_bfloat16 h[4], l[4];
#pragma unroll
    for (int j = 0; j < 4; ++j) {
        h[j] = __float2bfloat16(vv[j]);
        l[j] = __float2bfloat16(vv[j] - __bfloat162float(h[j]));
    }
    __nv_bfloat162* hp = (__nv_bfloat162*)(hi + i);
    __nv_bfloat162* lp = (__nv_bfloat162*)(lo + i);
    hp[0] = __halves2bfloat162(h[0], h[1]);
    hp[1] = __halves2bfloat162(h[2], h[3]);
    lp[0] = __halves2bfloat162(l[0], l[1]);
    lp[1] = __halves2bfloat162(l[2], l[3]);
}

// W [K, N] fp32 -> Wt_h/Wt_l [N, K] bf16
__global__ void transpose_split_kernel(const float* __restrict__ W,
                                       __nv_bfloat16* __restrict__ Th,
                                       __nv_bfloat16* __restrict__ Tl,
                                       int K, int N)
{
    __shared__ float tile[32][33];
    int n0 = blockIdx.x * 32, k0 = blockIdx.y * 32;
    int tx = threadIdx.x, ty = threadIdx.y;   // 32 x 8
#pragma unroll
    for (int j = 0; j < 32; j += 8)
        tile[ty + j][tx] = W[(size_t)(k0 + ty + j) * N + n0 + tx];
    __syncthreads();
#pragma unroll
    for (int j = 0; j < 32; j += 8) {
        float v = tile[tx][ty + j];
        __nv_bfloat16 h = __float2bfloat16(v);
        __nv_bfloat16 l = __float2bfloat16(v - __bfloat162float(h));
        size_t idx = (size_t)(n0 + ty + j) * K + k0 + tx;
        Th[idx] = h;
        Tl[idx] = l;
    }
}

// ---------------------------------------------------------------------------
// mma.sync bf16x3 GEMM: C[M,N] = A[M,K] @ B[N,K]^T + bias, fp32 out.
// CTA 128x128, BK=64, 8 warps (4x2), warp tile 32x64, 2-stage cp.async pipe.
// ---------------------------------------------------------------------------
#define TILE_B 16384                       // one 128x64 bf16 tile
#define STAGE_B (4 * TILE_B)               // Ah, Al, Bh, Bl
#define GEMM_SMEM (2 * STAGE_B)            // 128 KB

__global__ __launch_bounds__(256) void gemm_mma_kernel(
    const __nv_bfloat16* __restrict__ Ah, const __nv_bfloat16* __restrict__ Al,
    const __nv_bfloat16* __restrict__ Bh, const __nv_bfloat16* __restrict__ Bl,
    const float* __restrict__ bias, float* __restrict__ C,
    int M, int N, int K)
{
    extern __shared__ char smem[];
    const uint32_t sbase = smem_u32(smem);

    const int t   = threadIdx.x;
    const int wid = t >> 5;
    const int lid = t & 31;
    const int n0  = blockIdx.x * 128;
    const int m0  = blockIdx.y * 128;
    const int wm  = (wid & 3) * 32;        // warp m offset in tile
    const int wn  = (wid >> 2) * 64;       // warp n offset in tile

    const __nv_bfloat16* gsrc[4] = {
        Ah + (size_t)m0 * K, Al + (size_t)m0 * K,
        Bh + (size_t)n0 * K, Bl + (size_t)n0 * K };

    float acc[2][8][4];
#pragma unroll
    for (int mt = 0; mt < 2; ++mt)
#pragma unroll
        for (int nt = 0; nt < 8; ++nt)
#pragma unroll
            for (int e = 0; e < 4; ++e) acc[mt][nt][e] = 0.f;

    // cp.async loader for one stage/chunk
    auto load_stage = [&](int stage, int k0) {
        uint32_t sb = sbase + stage * STAGE_B;
#pragma unroll
        for (int tl = 0; tl < 4; ++tl) {
            const __nv_bfloat16* g = gsrc[tl] + k0;
#pragma unroll
            for (int i = 0; i < 4; ++i) {
                int idx = t + i * 256;           // 0..1023
                int row = idx >> 3;              // 0..127
                int j   = idx & 7;               // 16B group within 128B row
                const void* src = g + (size_t)row * K + j * 8;
                uint32_t dst = sb + tl * TILE_B + row * 128 + ((j ^ (row & 7)) << 4);
                CP_ASYNC16(dst, src);
            }
        }
    };

    // ldmatrix lane addressing (x4): lanes 0-7 m0-7/klo, 8-15 m8-15/klo,
    // 16-23 m0-7/khi, 24-31 m8-15/khi
    const int lrow8 = (lid & 7) + ((lid >> 3) & 1) * 8;   // 0..15
    const int lk    = (lid >> 4) & 1;                     // k-half

    const int nk = K / 64;
    load_stage(0, 0);
    CP_COMMIT();

    for (int c = 0; c < nk; ++c) {
        const int s = c & 1;
        if (c + 1 < nk) {
            load_stage(s ^ 1, (c + 1) * 64);
            CP_COMMIT();
            CP_WAIT(1);
        } else {
            CP_WAIT(0);
        }
        __syncthreads();

        const uint32_t sb = sbase + s * STAGE_B;
        const uint32_t aH = sb, aL = sb + TILE_B;
        const uint32_t bH = sb + 2 * TILE_B, bL = sb + 3 * TILE_B;

#pragma unroll
        for (int k16 = 0; k16 < 4; ++k16) {
            const int jg = k16 * 2 + lk;

            uint32_t bh[16], bl[16];
#pragma unroll
            for (int nb = 0; nb < 4; ++nb) {
                int row = wn + nb * 16 + lrow8;
                uint32_t off = row * 128 + ((jg ^ (row & 7)) << 4);
                ldsm4(&bh[nb * 4], bH + off);
                ldsm4(&bl[nb * 4], bL + off);
            }
#pragma unroll
            for (int mt = 0; mt < 2; ++mt) {
                int row = wm + mt * 16 + lrow8;
                uint32_t off = row * 128 + ((jg ^ (row & 7)) << 4);
                uint32_t ah[4], al[4];
                ldsm4(ah, aH + off);
                ldsm4(al, aL + off);
#pragma unroll
                for (int nb = 0; nb < 4; ++nb) {
                    // n-tile 2nb:   b = {r0, r2};  n-tile 2nb+1: b = {r1, r3}
                    mma16816(acc[mt][2 * nb],     ah, bh[nb * 4 + 0], bh[nb * 4 + 2]);
                    mma16816(acc[mt][2 * nb],     al, bh[nb * 4 + 0], bh[nb * 4 + 2]);
                    mma16816(acc[mt][2 * nb],     ah, bl[nb * 4 + 0], bl[nb * 4 + 2]);
                    mma16816(acc[mt][2 * nb + 1], ah, bh[nb * 4 + 1], bh[nb * 4 + 3]);
                    mma16816(acc[mt][2 * nb + 1], al, bh[nb * 4 + 1], bh[nb * 4 + 3]);
                    mma16816(acc[mt][2 * nb + 1], ah, bl[nb * 4 + 1], bl[nb * 4 + 3]);
                }
            }
        }
        __syncthreads();
    }

    // Epilogue: fragment layout d0..d3 -> (gid, tig*2), (gid, +1), (gid+8, ..)
    const int gid = lid >> 2;
    const int tig = lid & 3;
#pragma unroll
    for (int mt = 0; mt < 2; ++mt) {
        int m = m0 + wm + mt * 16 + gid;
#pragma unroll
        for (int nt = 0; nt < 8; ++nt) {
            int n = n0 + wn + nt * 8 + tig * 2;
            float b0 = bias[n], b1 = bias[n + 1];
            float* r0 = C + (size_t)m * N + n;
            float* r1 = C + (size_t)(m + 8) * N + n;
            *(float2*)r0 = make_float2(acc[mt][nt][0] + b0, acc[mt][nt][1] + b1);
            *(float2*)r1 = make_float2(acc[mt][nt][2] + b0, acc[mt][nt][3] + b1);
        }
    }
}

// ---------------------------------------------------------------------------
// Flash attention (causal), fp32 — unchanged from R1 (correct, fma-bound)
// ---------------------------------------------------------------------------
#define QT_PITCH 68
#define ATTN_SMEM_FLOATS (128 * QT_PITCH * 2 + 64 * 128 + 64 * QT_PITCH)

__global__ __launch_bounds__(256) void attn_kernel()
{
    extern __shared__ float sm[];
    float* Qt = sm;
    float* Kt = Qt + 128 * QT_PITCH;
    float* Vs = Kt + 128 * QT_PITCH;
    float* Ps = Vs + 64 * 128;

    const int t  = threadIdx.x;
    const int tx = t & 15;
    const int ty = t >> 4;
    const int qt = blockIdx.x;
    const int h  = blockIdx.y;
    const int b  = blockIdx.z;

    const size_t rstride = 3 * Cdim;
    const float* qbase = g_qkv + (size_t)b * Sdim * rstride + (size_t)h * Ddim;
    const float* kbase = qbase + Cdim;
    const float* vbase = qbase + 2 * Cdim;
    const int m0 = qt * 64;

    {
        const int r  = t >> 2;
        const int c4 = (t & 3) * 4;
#pragma unroll
        for (int i = 0; i < 8; ++i) {
            int d = c4 + i * 16;
            float4 qv = *(const float4*)(qbase + (size_t)(m0 + r) * rstride + d);
            Qt[(d + 0) * QT_PITCH + r] = qv.x;
            Qt[(d + 1) * QT_PITCH + r] = qv.y;
            Qt[(d + 2) * QT_PITCH + r] = qv.z;
            Qt[(d + 3) * QT_PITCH + r] = qv.w;
        }
    }

    float m_i[4], l_i[4], o[4][8];
#pragma unroll
    for (int i = 0; i < 4; ++i) {
        m_i[i] = -1e30f;
        l_i[i] = 0.f;
#pragma unroll
        for (int j = 0; j < 8; ++j) o[i][j] = 0.f;
    }

    const float scale = 0.08838834764831845f;

    for (int kt = 0; kt <= qt; ++kt) {
        const int n0 = kt * 64;
        __syncthreads();
        {
            const int r  = t >> 2;
            const int c4 = (t & 3) * 4;
#pragma unroll
            for (int i = 0; i < 8; ++i) {
                int d = c4 + i * 16;
                float4 kv = *(const float4*)(kbase + (size_t)(n0 + r) * rstride + d);
                Kt[(d + 0) * QT_PITCH + r] = kv.x;
                Kt[(d + 1) * QT_PITCH + r] = kv.y;
                Kt[(d + 2) * QT_PITCH + r] = kv.z;
                Kt[(d + 3) * QT_PITCH + r] = kv.w;
            }
#pragma unroll
            for (int i = 0; i < 8; ++i) {
                int idx = t + i * 256;
                int r2 = idx >> 5;
                int c  = (idx & 31) * 4;
                *(float4*)(&Vs[r2 * 128 + c]) =
                    *(const float4*)(vbase + (size_t)(n0 + r2) * rstride + c);
            }
        }
        __syncthreads();

        float s[4][4];
#pragma unroll
        for (int i = 0; i < 4; ++i)
#pragma unroll
            for (int j = 0; j < 4; ++j) s[i][j] = 0.f;

#pragma unroll 4
        for (int d = 0; d < 128; ++d) {
            float4 qa  = *(const float4*)(&Qt[d * QT_PITCH + ty * 4]);
            float4 kb4 = *(const float4*)(&Kt[d * QT_PITCH + tx * 4]);
            float a[4]  = {qa.x, qa.y, qa.z, qa.w};
            float bb[4] = {kb4.x, kb4.y, kb4.z, kb4.w};
#pragma unroll
            for (int i = 0; i < 4; ++i)
#pragma unroll
                for (int j = 0; j < 4; ++j)
                    s[i][j] = fmaf(a[i], bb[j], s[i][j]);
        }

        const bool diag = (kt == qt);
#pragma unroll
        for (int i = 0; i < 4; ++i) {
            int qrow = m0 + ty * 4 + i;
#pragma unroll
            for (int j = 0; j < 4; ++j) {
                s[i][j] *= scale;
                int kcol = n0 + tx * 4 + j;
                if (diag && kcol > qrow) s[i][j] = -1e30f;
            }
        }

#pragma unroll
        for (int i = 0; i < 4; ++i) {
            float mx = fmaxf(fmaxf(s[i][0], s[i][1]), fmaxf(s[i][2], s[i][3]));
#pragma unroll
            for (int w = 8; w >= 1; w >>= 1)
                mx = fmaxf(mx, __shfl_xor_sync(0xffffffffu, mx, w));
            float m_new = fmaxf(m_i[i], mx);
            float alpha = __expf(m_i[i] - m_new);
            float sum = 0.f;
#pragma unroll
            for (int j = 0; j < 4; ++j) {
                float p = __expf(s[i][j] - m_new);
                s[i][j] = p;
                sum += p;
            }
#pragma unroll
            for (int w = 8; w >= 1; w >>= 1)
                sum += __shfl_xor_sync(0xffffffffu, sum, w);
            l_i[i] = l_i[i] * alpha + sum;
            m_i[i] = m_new;
#pragma unroll
            for (int c = 0; c < 8; ++c) o[i][c] *= alpha;
#pragma unroll
            for (int j = 0; j < 4; ++j)
                Ps[(ty * 4 + i) * QT_PITCH + tx * 4 + j] = s[i][j];
        }
        __syncthreads();

#pragma unroll 2
        for (int j = 0; j < 64; ++j) {
            float p[4];
#pragma unroll
            for (int i = 0; i < 4; ++i)
                p[i] = Ps[(ty * 4 + i) * QT_PITCH + j];
            float4 v0 = *(const float4*)(&Vs[j * 128 + tx * 4]);
            float4 v1 = *(const float4*)(&Vs[j * 128 + 64 + tx * 4]);
            float v[8] = {v0.x, v0.y, v0.z, v0.w, v1.x, v1.y, v1.z, v1.w};
#pragma unroll
            for (int i = 0; i < 4; ++i)
#pragma unroll
                for (int c = 0; c < 8; ++c)
                    o[i][c] = fmaf(p[i], v[c], o[i][c]);
        }
    }

    float* ybase = g_y + (size_t)b * Sdim * Cdim + (size_t)h * Ddim;
#pragma unroll
    for (int i = 0; i < 4; ++i) {
        float inv = 1.0f / l_i[i];
        size_t rowoff = (size_t)(m0 + ty * 4 + i) * Cdim;
        *(float4*)(ybase + rowoff + tx * 4) =
            make_float4(o[i][0] * inv, o[i][1] * inv, o[i][2] * inv, o[i][3] * inv);
        *(float4*)(ybase + rowoff + 64 + tx * 4) =
            make_float4(o[i][4] * inv, o[i][5] * inv, o[i][6] * inv, o[i][7] * inv);
    }
}

// ---------------------------------------------------------------------------
// Launch
// ---------------------------------------------------------------------------
extern "C" void kernel_launch(void* const* d_in, const int* in_sizes, int n_in,
                              void* d_out, int out_size)
{
    const float* x      = (const float*)d_in[0];
    const float* w_qkv  = (const float*)d_in[1];
    const float* b_qkv  = (const float*)d_in[2];
    const float* w_proj = (const float*)d_in[3];
    const float* b_proj = (const float*)d_in[4];
    float* out = (float*)d_out;

    float *qkv, *y;
    __nv_bfloat16 *xh, *xl, *yh, *yl, *wqh, *wql, *wph, *wpl;
    cudaGetSymbolAddress((void**)&qkv, g_qkv);
    cudaGetSymbolAddress((void**)&y,   g_y);
    cudaGetSymbolAddress((void**)&xh,  g_xh);
    cudaGetSymbolAddress((void**)&xl,  g_xl);
    cudaGetSymbolAddress((void**)&yh,  g_yh);
    cudaGetSymbolAddress((void**)&yl,  g_yl);
    cudaGetSymbolAddress((void**)&wqh, g_wqkvT_h);
    cudaGetSymbolAddress((void**)&wql, g_wqkvT_l);
    cudaGetSymbolAddress((void**)&wph, g_wprojT_h);
    cudaGetSymbolAddress((void**)&wpl, g_wprojT_l);

    cudaFuncSetAttribute(gemm_mma_kernel,
                         cudaFuncAttributeMaxDynamicSharedMemorySize, GEMM_SMEM);

    // 1) splits
    {
        int n = Mtok * Cdim;
        split_kernel<<<(n / 4 + 255) / 256, 256>>>(x, xh, xl, n);
    }
    transpose_split_kernel<<<dim3(3 * Cdim / 32, Cdim / 32), dim3(32, 8)>>>(
        w_qkv, wqh, wql, Cdim, 3 * Cdim);
    transpose_split_kernel<<<dim3(Cdim / 32, Cdim / 32), dim3(32, 8)>>>(
        w_proj, wph, wpl, Cdim, Cdim);

    // 2) qkv = x @ w_qkv + b_qkv   [8192, 6144]  (tensor cores, bf16x3)
    gemm_mma_kernel<<<dim3(3 * Cdim / 128, Mtok / 128), 256, GEMM_SMEM>>>(
        xh, xl, wqh, wql, b_qkv, qkv, Mtok, 3 * Cdim, Cdim);

    // 3) flash attention -> y
    {
        size_t smem = ATTN_SMEM_FLOATS * sizeof(float);
        cudaFuncSetAttribute(attn_kernel,
                             cudaFuncAttributeMaxDynamicSharedMemorySize, (int)smem);
        dim3 grid(Sdim / 64, Hdim, Bdim);
        attn_kernel<<<grid, 256, smem>>>();
    }

    // 4) split y, then out = y @ w_proj + b_proj   [8192, 2048]
    {
        int n = Mtok * Cdim;
        split_kernel<<<(n / 4 + 255) / 256, 256>>>(y, yh, yl, n);
    }
    gemm_mma_kernel<<<dim3(Cdim / 128, Mtok / 128), 256, GEMM_SMEM>>>(
        yh, yl, wph, wpl, b_proj, out, Mtok, Cdim, Cdim);
}

// round 4
// speedup vs baseline: 2.4728x; 1.5192x over previous
#include <cuda_runtime.h>
#include <cuda_bf16.h>
#include <cstdint>

// Problem constants
#define Cdim 2048
#define Sdim 2048
#define Bdim 4
#define Hdim 16
#define Ddim 128
#define Mtok (Bdim * Sdim)          // 8192

// ---------------------------------------------------------------------------
// Scratch (device globals — no allocation allowed)
// ---------------------------------------------------------------------------
__device__ float g_qkv[(size_t)Mtok * 3 * Cdim];            // [8192, 6144] fp32
__device__ __nv_bfloat16 g_xh[(size_t)Mtok * Cdim];
__device__ __nv_bfloat16 g_xl[(size_t)Mtok * Cdim];
__device__ __nv_bfloat16 g_yh[(size_t)Mtok * Cdim];
__device__ __nv_bfloat16 g_yl[(size_t)Mtok * Cdim];
__device__ __nv_bfloat16 g_wqkvT_h[(size_t)3 * Cdim * Cdim];  // [6144, 2048] (N,K)
__device__ __nv_bfloat16 g_wqkvT_l[(size_t)3 * Cdim * Cdim];
__device__ __nv_bfloat16 g_wprojT_h[(size_t)Cdim * Cdim];     // [2048, 2048]
__device__ __nv_bfloat16 g_wprojT_l[(size_t)Cdim * Cdim];

// ---------------------------------------------------------------------------
// PTX helpers (base-ISA only: cp.async / ldmatrix / mma.sync)
// ---------------------------------------------------------------------------
__device__ __forceinline__ uint32_t smem_u32(const void* p) {
    uint32_t a;
    asm("{ .reg .u64 t; cvta.to.shared.u64 t, %1; cvt.u32.u64 %0, t; }" : "=r"(a) : "l"(p));
    return a;
}

#define CP_ASYNC16(dst, src) \
    asm volatile("cp.async.cg.shared.global [%0], [%1], 16;" :: "r"(dst), "l"(src))
#define CP_COMMIT() asm volatile("cp.async.commit_group;" ::: "memory")
#define CP_WAIT(n)  asm volatile("cp.async.wait_group %0;" :: "n"(n) : "memory")

__device__ __forceinline__ void ldsm4(uint32_t* r, uint32_t addr) {
    asm volatile("ldmatrix.sync.aligned.m8n8.x4.shared.b16 {%0,%1,%2,%3}, [%4];"
                 : "=r"(r[0]), "=r"(r[1]), "=r"(r[2]), "=r"(r[3]) : "r"(addr));
}
__device__ __forceinline__ void ldsm4t(uint32_t* r, uint32_t addr) {
    asm volatile("ldmatrix.sync.aligned.m8n8.x4.trans.shared.b16 {%0,%1,%2,%3}, [%4];"
                 : "=r"(r[0]), "=r"(r[1]), "=r"(r[2]), "=r"(r[3]) : "r"(addr));
}

__device__ __forceinline__ void mma16816(float* d, const uint32_t* a,
                                         uint32_t b0, uint32_t b1) {
    asm volatile(
        "mma.sync.aligned.m16n8k16.row.col.f32.bf16.bf16.f32 "
        "{%0,%1,%2,%3}, {%4,%5,%6,%7}, {%8,%9}, {%0,%1,%2,%3};"
        : "+f"(d[0]), "+f"(d[1]), "+f"(d[2]), "+f"(d[3])
        : "r"(a[0]), "r"(a[1]), "r"(a[2]), "r"(a[3]), "r"(b0), "r"(b1));
}

// pack two fp32 -> bf16x2 (lo in low half, hi in high half)
__device__ __forceinline__ uint32_t pack_bf16(float lo, float hi) {
    uint32_t r;
    asm("cvt.rn.bf16x2.f32 %0, %1, %2;" : "=r"(r) : "f"(hi), "f"(lo));
    return r;
}

#define STS128(addr, v0, v1, v2, v3) \
    asm volatile("st.shared.v4.b32 [%0], {%1,%2,%3,%4};" \
                 :: "r"(addr), "r"(v0), "r"(v1), "r"(v2), "r"(v3))

// split 8 fp32 into bf16 hi/lo 16B groups and store to swizzled smem
__device__ __forceinline__ void split8_store(float4 v0, float4 v1,
                                             uint32_t dh, uint32_t dl) {
    float f[8] = {v0.x, v0.y, v0.z, v0.w, v1.x, v1.y, v1.z, v1.w};
    uint32_t hh[4], ll[4];
#pragma unroll
    for (int p = 0; p < 4; ++p) {
        uint32_t pk = pack_bf16(f[2 * p], f[2 * p + 1]);
        float b0 = __uint_as_float(pk << 16);
        float b1 = __uint_as_float(pk & 0xFFFF0000u);
        hh[p] = pk;
        ll[p] = pack_bf16(f[2 * p] - b0, f[2 * p + 1] - b1);
    }
    STS128(dh, hh[0], hh[1], hh[2], hh[3]);
    STS128(dl, ll[0], ll[1], ll[2], ll[3]);
}

// ---------------------------------------------------------------------------
// Conversion kernels (fp32 -> bf16 hi/lo split)
// ---------------------------------------------------------------------------
__global__ void split_kernel(const float* __restrict__ in,
                             __nv_bfloat16* __restrict__ hi,
                             __nv_bfloat16* __restrict__ lo, int n)
{
    int i = (blockIdx.x * blockDim.x + threadIdx.x) * 4;
    if (i >= n) return;
    float4 v = *(const float4*)(in + i);
    float vv[4] = {v.x, v.y, v.z, v.w};
    uint32_t hp[2], lp[2];
#pragma unroll
    for (int p = 0; p < 2; ++p) {
        uint32_t pk = pack_bf16(vv[2 * p], vv[2 * p + 1]);
        float b0 = __uint_as_float(pk << 16);
        float b1 = __uint_as_float(pk & 0xFFFF0000u);
        hp[p] = pk;
        lp[p] = pack_bf16(vv[2 * p] - b0, vv[2 * p + 1] - b1);
    }
    *(uint2*)(hi + i) = make_uint2(hp[0], hp[1]);
    *(uint2*)(lo + i) = make_uint2(lp[0], lp[1]);
}

// W [K, N] fp32 -> Wt_h/Wt_l [N, K] bf16
__global__ void transpose_split_kernel(const float* __restrict__ W,
                                       __nv_bfloat16* __restrict__ Th,
                                       __nv_bfloat16* __restrict__ Tl,
                                       int K, int N)
{
    __shared__ float tile[32][33];
    int n0 = blockIdx.x * 32, k0 = blockIdx.y * 32;
    int tx = threadIdx.x, ty = threadIdx.y;   // 32 x 8
#pragma unroll
    for (int j = 0; j < 32; j += 8)
        tile[ty + j][tx] = W[(size_t)(k0 + ty + j) * N + n0 + tx];
    __syncthreads();
#pragma unroll
    for (int j = 0; j < 32; j += 8) {
        float v = tile[tx][ty + j];
        __nv_bfloat16 h = __float2bfloat16(v);
        __nv_bfloat16 l = __float2bfloat16(v - __bfloat162float(h));
        size_t idx = (size_t)(n0 + ty + j) * K + k0 + tx;
        Th[idx] = h;
        Tl[idx] = l;
    }
}

// ---------------------------------------------------------------------------
// mma.sync bf16x3 GEMM (unchanged from R3 — 61.8% tensor)
// ---------------------------------------------------------------------------
#define TILE_B 16384
#define STAGE_B (4 * TILE_B)
#define GEMM_SMEM (2 * STAGE_B)

__global__ __launch_bounds__(256) void gemm_mma_kernel(
    const __nv_bfloat16* __restrict__ Ah, const __nv_bfloat16* __restrict__ Al,
    const __nv_bfloat16* __restrict__ Bh, const __nv_bfloat16* __restrict__ Bl,
    const float* __restrict__ bias, float* __restrict__ C,
    int M, int N, int K)
{
    extern __shared__ char smem[];
    const uint32_t sbase = smem_u32(smem);

    const int t   = threadIdx.x;
    const int wid = t >> 5;
    const int lid = t & 31;
    const int n0  = blockIdx.x * 128;
    const int m0  = blockIdx.y * 128;
    const int wm  = (wid & 3) * 32;
    const int wn  = (wid >> 2) * 64;

    const __nv_bfloat16* gsrc[4] = {
        Ah + (size_t)m0 * K, Al + (size_t)m0 * K,
        Bh + (size_t)n0 * K, Bl + (size_t)n0 * K };

    float acc[2][8][4];
#pragma unroll
    for (int mt = 0; mt < 2; ++mt)
#pragma unroll
        for (int nt = 0; nt < 8; ++nt)
#pragma unroll
            for (int e = 0; e < 4; ++e) acc[mt][nt][e] = 0.f;

    auto load_stage = [&](int stage, int k0) {
        uint32_t sb = sbase + stage * STAGE_B;
#pragma unroll
        for (int tl = 0; tl < 4; ++tl) {
            const __nv_bfloat16* g = gsrc[tl] + k0;
#pragma unroll
            for (int i = 0; i < 4; ++i) {
                int idx = t + i * 256;
                int row = idx >> 3;
                int j   = idx & 7;
                const void* src = g + (size_t)row * K + j * 8;
                uint32_t dst = sb + tl * TILE_B + row * 128 + ((j ^ (row & 7)) << 4);
                CP_ASYNC16(dst, src);
            }
        }
    };

    const int lrow8 = (lid & 7) + ((lid >> 3) & 1) * 8;
    const int lk    = (lid >> 4) & 1;

    const int nk = K / 64;
    load_stage(0, 0);
    CP_COMMIT();

    for (int c = 0; c < nk; ++c) {
        const int s = c & 1;
        if (c + 1 < nk) {
            load_stage(s ^ 1, (c + 1) * 64);
            CP_COMMIT();
            CP_WAIT(1);
        } else {
            CP_WAIT(0);
        }
        __syncthreads();

        const uint32_t sb = sbase + s * STAGE_B;
        const uint32_t aH = sb, aL = sb + TILE_B;
        const uint32_t bH = sb + 2 * TILE_B, bL = sb + 3 * TILE_B;

#pragma unroll
        for (int k16 = 0; k16 < 4; ++k16) {
            const int jg = k16 * 2 + lk;

            uint32_t bh[16], bl[16];
#pragma unroll
            for (int nb = 0; nb < 4; ++nb) {
                int row = wn + nb * 16 + lrow8;
                uint32_t off = row * 128 + ((jg ^ (row & 7)) << 4);
                ldsm4(&bh[nb * 4], bH + off);
                ldsm4(&bl[nb * 4], bL + off);
            }
#pragma unroll
            for (int mt = 0; mt < 2; ++mt) {
                int row = wm + mt * 16 + lrow8;
                uint32_t off = row * 128 + ((jg ^ (row & 7)) << 4);
                uint32_t ah[4], al[4];
                ldsm4(ah, aH + off);
                ldsm4(al, aL + off);
#pragma unroll
                for (int nb = 0; nb < 4; ++nb) {
                    mma16816(acc[mt][2 * nb],     ah, bh[nb * 4 + 0], bh[nb * 4 + 2]);
                    mma16816(acc[mt][2 * nb],     al, bh[nb * 4 + 0], bh[nb * 4 + 2]);
                    mma16816(acc[mt][2 * nb],     ah, bl[nb * 4 + 0], bl[nb * 4 + 2]);
                    mma16816(acc[mt][2 * nb + 1], ah, bh[nb * 4 + 1], bh[nb * 4 + 3]);
                    mma16816(acc[mt][2 * nb + 1], al, bh[nb * 4 + 1], bh[nb * 4 + 3]);
                    mma16816(acc[mt][2 * nb + 1], ah, bl[nb * 4 + 1], bl[nb * 4 + 3]);
                }
            }
        }
        __syncthreads();
    }

    const int gid = lid >> 2;
    const int tig = lid & 3;
#pragma unroll
    for (int mt = 0; mt < 2; ++mt) {
        int m = m0 + wm + mt * 16 + gid;
#pragma unroll
        for (int nt = 0; nt < 8; ++nt) {
            int n = n0 + wn + nt * 8 + tig * 2;
            float b0 = bias[n], b1 = bias[n + 1];
            float* r0 = C + (size_t)m * N + n;
            float* r1 = C + (size_t)(m + 8) * N + n;
            *(float2*)r0 = make_float2(acc[mt][nt][0] + b0, acc[mt][nt][1] + b1);
            *(float2*)r1 = make_float2(acc[mt][nt][2] + b0, acc[mt][nt][3] + b1);
        }
    }
}

// ---------------------------------------------------------------------------
// Flash attention with mma.sync (bf16x3 QK and PV), causal.
// CTA: 128 q-rows, 64-kv chunks. 8 warps x 16 q-rows. fp32 softmax/accum.
// Smem: Qh/Ql [128][128]b16 + Kh/Kl [64][128] + Vh/Vl [64][128]  (128 KB)
// Writes yh/yl bf16 directly (proj GEMM consumes them).
// ---------------------------------------------------------------------------
#define QTILE_B (128 * 256)
#define KTILE_B (64 * 256)
#define ATTN_SMEM (2 * QTILE_B + 4 * KTILE_B)   // 131072

__global__ __launch_bounds__(256) void attn_mma_kernel()
{
    extern __shared__ char sm8[];
    const uint32_t sb  = smem_u32(sm8);
    const uint32_t sQh = sb, sQl = sb + QTILE_B;
    const uint32_t sKh = sb + 2 * QTILE_B, sKl = sKh + KTILE_B;
    const uint32_t sVh = sKl + KTILE_B,    sVl = sVh + KTILE_B;

    const int t   = threadIdx.x;
    const int wid = t >> 5;
    const int lid = t & 31;
    const int qt  = blockIdx.x;             // 0..15
    const int h   = blockIdx.y;
    const int b   = blockIdx.z;
    const int m0  = qt * 128;
    const int wm  = wid * 16;
    const int gid = lid >> 2;
    const int tig = lid & 3;
    const int lrow8 = (lid & 7) + ((lid >> 3) & 1) * 8;
    const int lk    = (lid >> 4) & 1;

    const size_t rstride = 3 * Cdim;
    const float* qbase = g_qkv + (size_t)b * Sdim * rstride + (size_t)h * Ddim;
    const float* kbase = qbase + Cdim;
    const float* vbase = qbase + 2 * Cdim;

    // Load Q tile -> bf16 hi/lo swizzled smem. 2048 16B-segments.
#pragma unroll
    for (int i = 0; i < 8; ++i) {
        int idx = t + i * 256;
        int row = idx >> 4, j = idx & 15;
        const float4* src = (const float4*)(qbase + (size_t)(m0 + row) * rstride + j * 8);
        uint32_t off = row * 256 + ((j ^ (row & 7)) << 4);
        split8_store(src[0], src[1], sQh + off, sQl + off);
    }

    float o[16][4];
    float m_i[2] = {-1e30f, -1e30f};
    float l_i[2] = {0.f, 0.f};
#pragma unroll
    for (int nt = 0; nt < 16; ++nt)
#pragma unroll
        for (int e = 0; e < 4; ++e) o[nt][e] = 0.f;

    const float scale = 0.08838834764831845f;   // 1/sqrt(128)
    const int ktmax = (m0 >> 6) + 1;
    const int r0g = m0 + wm + gid;              // this lane's first q row

    for (int kt = 0; kt <= ktmax; ++kt) {
        const int n0 = kt << 6;
        __syncthreads();
        // Load K and V chunk (fp32 -> bf16 h/l). 1024 segments each.
#pragma unroll
        for (int i = 0; i < 4; ++i) {
            int idx = t + i * 256;
            int row = idx >> 4, j = idx & 15;
            uint32_t off = row * 256 + ((j ^ (row & 7)) << 4);
            const float4* ks = (const float4*)(kbase + (size_t)(n0 + row) * rstride + j * 8);
            split8_store(ks[0], ks[1], sKh + off, sKl + off);
            const float4* vs = (const float4*)(vbase + (size_t)(n0 + row) * rstride + j * 8);
            split8_store(vs[0], vs[1], sVh + off, sVl + off);
        }
        __syncthreads();

        // Warps whose entire 16-row span is masked for this chunk skip compute.
        if (m0 + wm + 15 < n0) continue;

        // ---- S = Q K^T (bf16x3) ----
        float s[8][4];
#pragma unroll
        for (int nt = 0; nt < 8; ++nt)
#pragma unroll
            for (int e = 0; e < 4; ++e) s[nt][e] = 0.f;

#pragma unroll
        for (int ks = 0; ks < 8; ++ks) {
            const int jg = ks * 2 + lk;
            const int arow = wm + lrow8;
            uint32_t aoff = arow * 256 + ((jg ^ (arow & 7)) << 4);
            uint32_t qh[4], ql[4];
            ldsm4(qh, sQh + aoff);
            ldsm4(ql, sQl + aoff);
#pragma unroll
            for (int g = 0; g < 4; ++g) {
                const int brow = g * 16 + lrow8;
                uint32_t boff = brow * 256 + ((jg ^ (brow & 7)) << 4);
                uint32_t kh[4], klf[4];
                ldsm4(kh,  sKh + boff);
                ldsm4(klf, sKl + boff);
                mma16816(s[2 * g],     qh, kh[0],  kh[2]);
                mma16816(s[2 * g],     ql, kh[0],  kh[2]);
                mma16816(s[2 * g],     qh, klf[0], klf[2]);
                mma16816(s[2 * g + 1], qh, kh[1],  kh[3]);
                mma16816(s[2 * g + 1], ql, kh[1],  kh[3]);
                mma16816(s[2 * g + 1], qh, klf[1], klf[3]);
            }
        }

        // scale + causal mask
        const bool diag = (n0 + 63 > m0 + wm);
#pragma unroll
        for (int nt = 0; nt < 8; ++nt) {
            const int c0 = n0 + nt * 8 + tig * 2;
#pragma unroll
            for (int e = 0; e < 4; ++e) s[nt][e] *= scale;
            if (diag) {
                if (c0     > r0g)     s[nt][0] = -1e30f;
                if (c0 + 1 > r0g)     s[nt][1] = -1e30f;
                if (c0     > r0g + 8) s[nt][2] = -1e30f;
                if (c0 + 1 > r0g + 8) s[nt][3] = -1e30f;
            }
        }

        // ---- online softmax (rows gid and gid+8) ----
#pragma unroll
        for (int rr = 0; rr < 2; ++rr) {
            float mx = -1e30f;
#pragma unroll
            for (int nt = 0; nt < 8; ++nt)
                mx = fmaxf(mx, fmaxf(s[nt][2 * rr], s[nt][2 * rr + 1]));
            mx = fmaxf(mx, __shfl_xor_sync(0xffffffffu, mx, 1));
            mx = fmaxf(mx, __shfl_xor_sync(0xffffffffu, mx, 2));
            float m_new = fmaxf(m_i[rr], mx);
            float alpha = __expf(m_i[rr] - m_new);
            float sum = 0.f;
#pragma unroll
            for (int nt = 0; nt < 8; ++nt) {
                float p0 = __expf(s[nt][2 * rr]     - m_new);
                float p1 = __expf(s[nt][2 * rr + 1] - m_new);
                s[nt][2 * rr]     = p0;
                s[nt][2 * rr + 1] = p1;
                sum += p0 + p1;
            }
            sum += __shfl_xor_sync(0xffffffffu, sum, 1);
            sum += __shfl_xor_sync(0xffffffffu, sum, 2);
            l_i[rr] = l_i[rr] * alpha + sum;
            m_i[rr] = m_new;
#pragma unroll
            for (int nt = 0; nt < 16; ++nt) {
                o[nt][2 * rr]     *= alpha;
                o[nt][2 * rr + 1] *= alpha;
            }
        }

        // ---- O += P V (bf16x3: PhVh + PlVh + PhVl) ----
        const int vrow_b = (lid & 7) + ((lid >> 3) & 1) * 8;
        const int vlk    = (lid >> 4) & 1;
#pragma unroll
        for (int j = 0; j < 4; ++j) {
            // A fragments from P (cols 16j..16j+15)
            uint32_t ah[4], al[4];
#pragma unroll
            for (int half = 0; half < 2; ++half) {
                const float* sp = s[2 * j + half];
#pragma unroll
                for (int rr = 0; rr < 2; ++rr) {
                    float p0 = sp[2 * rr], p1 = sp[2 * rr + 1];
                    uint32_t pk = pack_bf16(p0, p1);
                    float b0 = __uint_as_float(pk << 16);
                    float b1 = __uint_as_float(pk & 0xFFFF0000u);
                    ah[half * 2 + rr] = pk;
                    al[half * 2 + rr] = pack_bf16(p0 - b0, p1 - b1);
                }
            }
            const int vrow = j * 16 + vrow_b;
#pragma unroll
            for (int g = 0; g < 8; ++g) {
                const int jj = g * 2 + vlk;
                uint32_t voff = vrow * 256 + ((jj ^ (vrow & 7)) << 4);
                uint32_t vh[4], vl[4];
                ldsm4t(vh, sVh + voff);
                ldsm4t(vl, sVl + voff);
                mma16816(o[2 * g],     ah, vh[0], vh[1]);
                mma16816(o[2 * g],     al, vh[0], vh[1]);
                mma16816(o[2 * g],     ah, vl[0], vl[1]);
                mma16816(o[2 * g + 1], ah, vh[2], vh[3]);
                mma16816(o[2 * g + 1], al, vh[2], vh[3]);
                mma16816(o[2 * g + 1], ah, vl[2], vl[3]);
            }
        }
    }

    // ---- epilogue: normalize, split to bf16 h/l, write ----
    const float inv0 = 1.0f / l_i[0];
    const float inv1 = 1.0f / l_i[1];
    const size_t ybase = (size_t)b * Sdim * Cdim + (size_t)h * Ddim;
    __nv_bfloat16* yh = g_yh + ybase;
    __nv_bfloat16* yl = g_yl + ybase;
    const size_t row0 = (size_t)(m0 + wm + gid) * Cdim;
    const size_t row1 = row0 + 8 * Cdim;
#pragma unroll
    for (int nt = 0; nt < 16; ++nt) {
        const int col = nt * 8 + tig * 2;
        float p0 = o[nt][0] * inv0, p1 = o[nt][1] * inv0;
        uint32_t pk = pack_bf16(p0, p1);
        float b0 = __uint_as_float(pk << 16);
        float b1 = __uint_as_float(pk & 0xFFFF0000u);
        *(uint32_t*)(yh + row0 + col) = pk;
        *(uint32_t*)(yl + row0 + col) = pack_bf16(p0 - b0, p1 - b1);
        p0 = o[nt][2] * inv1; p1 = o[nt][3] * inv1;
        pk = pack_bf16(p0, p1);
        b0 = __uint_as_float(pk << 16);
        b1 = __uint_as_float(pk & 0xFFFF0000u);
        *(uint32_t*)(yh + row1 + col) = pk;
        *(uint32_t*)(yl + row1 + col) = pack_bf16(p0 - b0, p1 - b1);
    }
}

// ---------------------------------------------------------------------------
// Launch
// ---------------------------------------------------------------------------
extern "C" void kernel_launch(void* const* d_in, const int* in_sizes, int n_in,
                              void* d_out, int out_size)
{
    const float* x      = (const float*)d_in[0];
    const float* w_qkv  = (const float*)d_in[1];
    const float* b_qkv  = (const float*)d_in[2];
    const float* w_proj = (const float*)d_in[3];
    const float* b_proj = (const float*)d_in[4];
    float* out = (float*)d_out;

    float* qkv;
    __nv_bfloat16 *xh, *xl, *yh, *yl, *wqh, *wql, *wph, *wpl;
    cudaGetSymbolAddress((void**)&qkv, g_qkv);
    cudaGetSymbolAddress((void**)&xh,  g_xh);
    cudaGetSymbolAddress((void**)&xl,  g_xl);
    cudaGetSymbolAddress((void**)&yh,  g_yh);
    cudaGetSymbolAddress((void**)&yl,  g_yl);
    cudaGetSymbolAddress((void**)&wqh, g_wqkvT_h);
    cudaGetSymbolAddress((void**)&wql, g_wqkvT_l);
    cudaGetSymbolAddress((void**)&wph, g_wprojT_h);
    cudaGetSymbolAddress((void**)&wpl, g_wprojT_l);

    cudaFuncSetAttribute(gemm_mma_kernel,
                         cudaFuncAttributeMaxDynamicSharedMemorySize, GEMM_SMEM);
    cudaFuncSetAttribute(attn_mma_kernel,
                         cudaFuncAttributeMaxDynamicSharedMemorySize, ATTN_SMEM);

    // 1) splits
    {
        int n = Mtok * Cdim;
        split_kernel<<<(n / 4 + 255) / 256, 256>>>(x, xh, xl, n);
    }
    transpose_split_kernel<<<dim3(3 * Cdim / 32, Cdim / 32), dim3(32, 8)>>>(
        w_qkv, wqh, wql, Cdim, 3 * Cdim);
    transpose_split_kernel<<<dim3(Cdim / 32, Cdim / 32), dim3(32, 8)>>>(
        w_proj, wph, wpl, Cdim, Cdim);

    // 2) qkv = x @ w_qkv + b_qkv   [8192, 6144]
    gemm_mma_kernel<<<dim3(3 * Cdim / 128, Mtok / 128), 256, GEMM_SMEM>>>(
        xh, xl, wqh, wql, b_qkv, qkv, Mtok, 3 * Cdim, Cdim);

    // 3) flash attention (mma) -> yh/yl bf16
    {
        dim3 grid(Sdim / 128, Hdim, Bdim);
        attn_mma_kernel<<<grid, 256, ATTN_SMEM>>>();
    }

    // 4) out = y @ w_proj + b_proj   [8192, 2048]
    gemm_mma_kernel<<<dim3(Cdim / 128, Mtok / 128), 256, GEMM_SMEM>>>(
        yh, yl, wph, wpl, b_proj, out, Mtok, Cdim, Cdim);
}

// round 5
// speedup vs baseline: 2.6073x; 1.0544x over previous
#include <cuda_runtime.h>
#include <cuda_bf16.h>
#include <cstdint>

// Problem constants
#define Cdim 2048
#define Sdim 2048
#define Bdim 4
#define Hdim 16
#define Ddim 128
#define Mtok (Bdim * Sdim)          // 8192
#define QKV_N (3 * Cdim)            // 6144

// ---------------------------------------------------------------------------
// Scratch (device globals — no allocation allowed)
// ---------------------------------------------------------------------------
__device__ __nv_bfloat16 g_qkvh[(size_t)Mtok * QKV_N];      // qkv hi (bf16)
__device__ __nv_bfloat16 g_qkvl[(size_t)Mtok * QKV_N];      // qkv lo (bf16)
__device__ __nv_bfloat16 g_xh[(size_t)Mtok * Cdim];
__device__ __nv_bfloat16 g_xl[(size_t)Mtok * Cdim];
__device__ __nv_bfloat16 g_yh[(size_t)Mtok * Cdim];
__device__ __nv_bfloat16 g_yl[(size_t)Mtok * Cdim];
__device__ __nv_bfloat16 g_wqkvT_h[(size_t)QKV_N * Cdim];   // [6144, 2048] (N,K)
__device__ __nv_bfloat16 g_wqkvT_l[(size_t)QKV_N * Cdim];
__device__ __nv_bfloat16 g_wprojT_h[(size_t)Cdim * Cdim];   // [2048, 2048]
__device__ __nv_bfloat16 g_wprojT_l[(size_t)Cdim * Cdim];

// ---------------------------------------------------------------------------
// PTX helpers (base-ISA only: cp.async / ldmatrix / mma.sync)
// ---------------------------------------------------------------------------
__device__ __forceinline__ uint32_t smem_u32(const void* p) {
    uint32_t a;
    asm("{ .reg .u64 t; cvta.to.shared.u64 t, %1; cvt.u32.u64 %0, t; }" : "=r"(a) : "l"(p));
    return a;
}

#define CP_ASYNC16(dst, src) \
    asm volatile("cp.async.cg.shared.global [%0], [%1], 16;" :: "r"(dst), "l"(src))
#define CP_COMMIT() asm volatile("cp.async.commit_group;" ::: "memory")
#define CP_WAIT(n)  asm volatile("cp.async.wait_group %0;" :: "n"(n) : "memory")

__device__ __forceinline__ void ldsm4(uint32_t* r, uint32_t addr) {
    asm volatile("ldmatrix.sync.aligned.m8n8.x4.shared.b16 {%0,%1,%2,%3}, [%4];"
                 : "=r"(r[0]), "=r"(r[1]), "=r"(r[2]), "=r"(r[3]) : "r"(addr));
}
__device__ __forceinline__ void ldsm4t(uint32_t* r, uint32_t addr) {
    asm volatile("ldmatrix.sync.aligned.m8n8.x4.trans.shared.b16 {%0,%1,%2,%3}, [%4];"
                 : "=r"(r[0]), "=r"(r[1]), "=r"(r[2]), "=r"(r[3]) : "r"(addr));
}

__device__ __forceinline__ void mma16816(float* d, const uint32_t* a,
                                         uint32_t b0, uint32_t b1) {
    asm volatile(
        "mma.sync.aligned.m16n8k16.row.col.f32.bf16.bf16.f32 "
        "{%0,%1,%2,%3}, {%4,%5,%6,%7}, {%8,%9}, {%0,%1,%2,%3};"
        : "+f"(d[0]), "+f"(d[1]), "+f"(d[2]), "+f"(d[3])
        : "r"(a[0]), "r"(a[1]), "r"(a[2]), "r"(a[3]), "r"(b0), "r"(b1));
}

// pack two fp32 -> bf16x2 (first arg in low half)
__device__ __forceinline__ uint32_t pack_bf16(float lo, float hi) {
    uint32_t r;
    asm("cvt.rn.bf16x2.f32 %0, %1, %2;" : "=r"(r) : "f"(hi), "f"(lo));
    return r;
}

// ---------------------------------------------------------------------------
// Conversion kernels (fp32 -> bf16 hi/lo split)
// ---------------------------------------------------------------------------
__global__ void split_kernel(const float* __restrict__ in,
                             __nv_bfloat16* __restrict__ hi,
                             __nv_bfloat16* __restrict__ lo, int n)
{
    int i = (blockIdx.x * blockDim.x + threadIdx.x) * 4;
    if (i >= n) return;
    float4 v = *(const float4*)(in + i);
    float vv[4] = {v.x, v.y, v.z, v.w};
    uint32_t hp[2], lp[2];
#pragma unroll
    for (int p = 0; p < 2; ++p) {
        uint32_t pk = pack_bf16(vv[2 * p], vv[2 * p + 1]);
        float b0 = __uint_as_float(pk << 16);
        float b1 = __uint_as_float(pk & 0xFFFF0000u);
        hp[p] = pk;
        lp[p] = pack_bf16(vv[2 * p] - b0, vv[2 * p + 1] - b1);
    }
    *(uint2*)(hi + i) = make_uint2(hp[0], hp[1]);
    *(uint2*)(lo + i) = make_uint2(lp[0], lp[1]);
}

// W [K, N] fp32 -> Wt_h/Wt_l [N, K] bf16
__global__ void transpose_split_kernel(const float* __restrict__ W,
                                       __nv_bfloat16* __restrict__ Th,
                                       __nv_bfloat16* __restrict__ Tl,
                                       int K, int N)
{
    __shared__ float tile[32][33];
    int n0 = blockIdx.x * 32, k0 = blockIdx.y * 32;
    int tx = threadIdx.x, ty = threadIdx.y;   // 32 x 8
#pragma unroll
    for (int j = 0; j < 32; j += 8)
        tile[ty + j][tx] = W[(size_t)(k0 + ty + j) * N + n0 + tx];
    __syncthreads();
#pragma unroll
    for (int j = 0; j < 32; j += 8) {
        float v = tile[tx][ty + j];
        __nv_bfloat16 h = __float2bfloat16(v);
        __nv_bfloat16 l = __float2bfloat16(v - __bfloat162float(h));
        size_t idx = (size_t)(n0 + ty + j) * K + k0 + tx;
        Th[idx] = h;
        Tl[idx] = l;
    }
}

// ---------------------------------------------------------------------------
// mma.sync bf16x3 GEMM: C = A @ B^T + bias. 128x128 tile, BK=64,
// 3-stage cp.async pipeline, ONE __syncthreads per chunk.
// OUTM=0: fp32 C.  OUTM=1: split bf16 (Ch, Cl).
// ---------------------------------------------------------------------------
#define TILE_B 16384
#define STAGE_B (4 * TILE_B)               // 64 KB
#define GEMM_SMEM (3 * STAGE_B)            // 192 KB

template<int OUTM>
__global__ __launch_bounds__(256) void gemm_mma_kernel(
    const __nv_bfloat16* __restrict__ Ah, const __nv_bfloat16* __restrict__ Al,
    const __nv_bfloat16* __restrict__ Bh, const __nv_bfloat16* __restrict__ Bl,
    const float* __restrict__ bias, float* __restrict__ C,
    __nv_bfloat16* __restrict__ Ch, __nv_bfloat16* __restrict__ Cl,
    int M, int N, int K)
{
    extern __shared__ char smem[];
    const uint32_t sbase = smem_u32(smem);

    const int t   = threadIdx.x;
    const int wid = t >> 5;
    const int lid = t & 31;
    const int n0  = blockIdx.x * 128;
    const int m0  = blockIdx.y * 128;
    const int wm  = (wid & 3) * 32;
    const int wn  = (wid >> 2) * 64;

    const __nv_bfloat16* gsrc[4] = {
        Ah + (size_t)m0 * K, Al + (size_t)m0 * K,
        Bh + (size_t)n0 * K, Bl + (size_t)n0 * K };

    float acc[2][8][4];
#pragma unroll
    for (int mt = 0; mt < 2; ++mt)
#pragma unroll
        for (int nt = 0; nt < 8; ++nt)
#pragma unroll
            for (int e = 0; e < 4; ++e) acc[mt][nt][e] = 0.f;

    auto load_stage = [&](int stage, int k0) {
        uint32_t sb = sbase + stage * STAGE_B;
#pragma unroll
        for (int tl = 0; tl < 4; ++tl) {
            const __nv_bfloat16* g = gsrc[tl] + k0;
#pragma unroll
            for (int i = 0; i < 4; ++i) {
                int idx = t + i * 256;
                int row = idx >> 3;
                int j   = idx & 7;
                const void* src = g + (size_t)row * K + j * 8;
                uint32_t dst = sb + tl * TILE_B + row * 128 + ((j ^ (row & 7)) << 4);
                CP_ASYNC16(dst, src);
            }
        }
    };

    const int lrow8 = (lid & 7) + ((lid >> 3) & 1) * 8;
    const int lk    = (lid >> 4) & 1;

    const int nk = K / 64;
    load_stage(0, 0);
    CP_COMMIT();
    load_stage(1, 64);
    CP_COMMIT();

    for (int c = 0; c < nk; ++c) {
        CP_WAIT(1);                 // chunk c resident
        __syncthreads();            // all warps done with stage (c-1)%3
        if (c + 2 < nk) load_stage((c + 2) % 3, (c + 2) * 64);
        CP_COMMIT();                // always commit (possibly empty group)

        const uint32_t sb = sbase + (c % 3) * STAGE_B;
        const uint32_t aH = sb, aL = sb + TILE_B;
        const uint32_t bH = sb + 2 * TILE_B, bL = sb + 3 * TILE_B;

#pragma unroll
        for (int k16 = 0; k16 < 4; ++k16) {
            const int jg = k16 * 2 + lk;

            uint32_t bh[16], bl[16];
#pragma unroll
            for (int nb = 0; nb < 4; ++nb) {
                int row = wn + nb * 16 + lrow8;
                uint32_t off = row * 128 + ((jg ^ (row & 7)) << 4);
                ldsm4(&bh[nb * 4], bH + off);
                ldsm4(&bl[nb * 4], bL + off);
            }
#pragma unroll
            for (int mt = 0; mt < 2; ++mt) {
                int row = wm + mt * 16 + lrow8;
                uint32_t off = row * 128 + ((jg ^ (row & 7)) << 4);
                uint32_t ah[4], al[4];
                ldsm4(ah, aH + off);
                ldsm4(al, aL + off);
#pragma unroll
                for (int nb = 0; nb < 4; ++nb) {
                    mma16816(acc[mt][2 * nb],     ah, bh[nb * 4 + 0], bh[nb * 4 + 2]);
                    mma16816(acc[mt][2 * nb],     al, bh[nb * 4 + 0], bh[nb * 4 + 2]);
                    mma16816(acc[mt][2 * nb],     ah, bl[nb * 4 + 0], bl[nb * 4 + 2]);
                    mma16816(acc[mt][2 * nb + 1], ah, bh[nb * 4 + 1], bh[nb * 4 + 3]);
                    mma16816(acc[mt][2 * nb + 1], al, bh[nb * 4 + 1], bh[nb * 4 + 3]);
                    mma16816(acc[mt][2 * nb + 1], ah, bl[nb * 4 + 1], bl[nb * 4 + 3]);
                }
            }
        }
    }

    const int gid = lid >> 2;
    const int tig = lid & 3;
#pragma unroll
    for (int mt = 0; mt < 2; ++mt) {
        int m = m0 + wm + mt * 16 + gid;
#pragma unroll
        for (int nt = 0; nt < 8; ++nt) {
            int n = n0 + wn + nt * 8 + tig * 2;
            float b0 = bias[n], b1 = bias[n + 1];
            float v00 = acc[mt][nt][0] + b0, v01 = acc[mt][nt][1] + b1;
            float v10 = acc[mt][nt][2] + b0, v11 = acc[mt][nt][3] + b1;
            if (OUTM == 0) {
                *(float2*)(C + (size_t)m * N + n)       = make_float2(v00, v01);
                *(float2*)(C + (size_t)(m + 8) * N + n) = make_float2(v10, v11);
            } else {
                uint32_t pk = pack_bf16(v00, v01);
                float r0 = __uint_as_float(pk << 16);
                float r1 = __uint_as_float(pk & 0xFFFF0000u);
                *(uint32_t*)(Ch + (size_t)m * N + n) = pk;
                *(uint32_t*)(Cl + (size_t)m * N + n) = pack_bf16(v00 - r0, v01 - r1);
                pk = pack_bf16(v10, v11);
                r0 = __uint_as_float(pk << 16);
                r1 = __uint_as_float(pk & 0xFFFF0000u);
                *(uint32_t*)(Ch + (size_t)(m + 8) * N + n) = pk;
                *(uint32_t*)(Cl + (size_t)(m + 8) * N + n) = pack_bf16(v10 - r0, v11 - r1);
            }
        }
    }
}

// ---------------------------------------------------------------------------
// Flash attention with mma.sync (bf16x3 QK and PV), causal.
// Inputs: g_qkvh/g_qkvl (bf16 hi/lo, written by QKV GEMM).
// CTA: 128 q-rows x 64-kv chunks. 8 warps x 16 q-rows.
// Smem: Q h/l (64 KB) + 2-stage K/V h/l (2 x 64 KB) = 192 KB. cp.async loads.
// ---------------------------------------------------------------------------
#define KV_TILE_B 16384                     // 64 rows x 256 B
#define KV_STAGE_B (4 * KV_TILE_B)          // Kh, Kl, Vh, Vl
#define Q_TILE_B   32768                    // 128 rows x 256 B
#define ATTN_SMEM (2 * Q_TILE_B + 2 * KV_STAGE_B)   // 196608

__global__ __launch_bounds__(256) void attn_mma_kernel()
{
    extern __shared__ char sm8[];
    const uint32_t sb  = smem_u32(sm8);
    const uint32_t sQh = sb, sQl = sb + Q_TILE_B;
    const uint32_t sKV = sb + 2 * Q_TILE_B;

    const int t   = threadIdx.x;
    const int wid = t >> 5;
    const int lid = t & 31;
    const int qt  = blockIdx.x;             // 0..15
    const int h   = blockIdx.y;
    const int b   = blockIdx.z;
    const int m0  = qt * 128;
    const int wm  = wid * 16;
    const int gid = lid >> 2;
    const int tig = lid & 3;
    const int lrow8 = (lid & 7) + ((lid >> 3) & 1) * 8;
    const int lk    = (lid >> 4) & 1;

    const size_t tok0 = ((size_t)b * Sdim + m0) * QKV_N;
    const __nv_bfloat16* qh = g_qkvh + tok0 + h * Ddim;
    const __nv_bfloat16* ql = g_qkvl + tok0 + h * Ddim;
    const size_t kvtok = (size_t)b * Sdim * QKV_N;
    const __nv_bfloat16* kv_base[4] = {
        g_qkvh + kvtok + Cdim + h * Ddim,      // Kh
        g_qkvl + kvtok + Cdim + h * Ddim,      // Kl
        g_qkvh + kvtok + 2 * Cdim + h * Ddim,  // Vh
        g_qkvl + kvtok + 2 * Cdim + h * Ddim   // Vl
    };

    auto load_kv = [&](int stage, int n0) {
        uint32_t dstb = sKV + stage * KV_STAGE_B;
#pragma unroll
        for (int i = 0; i < 16; ++i) {
            int idx  = t + i * 256;            // 0..4095
            int tile = idx >> 10;
            int rem  = idx & 1023;
            int row  = rem >> 4, j = rem & 15;
            const void* src = kv_base[tile] + (size_t)(n0 + row) * QKV_N + j * 8;
            uint32_t dst = dstb + tile * KV_TILE_B + row * 256 + ((j ^ (row & 7)) << 4);
            CP_ASYNC16(dst, src);
        }
    };

    // Q tile loads (group 0, together with chunk 0)
#pragma unroll
    for (int i = 0; i < 16; ++i) {
        int idx  = t + i * 256;                // 0..4095
        int tile = idx >> 11;                  // 0: Qh, 1: Ql
        int rem  = idx & 2047;
        int row  = rem >> 4, j = rem & 15;
        const __nv_bfloat16* src = (tile == 0 ? qh : ql) + (size_t)row * QKV_N + j * 8;
        uint32_t dst = (tile == 0 ? sQh : sQl) + row * 256 + ((j ^ (row & 7)) << 4);
        CP_ASYNC16(dst, src);
    }
    load_kv(0, 0);
    CP_COMMIT();                               // group: Q + chunk0
    const int ktmax = (m0 >> 6) + 1;
    if (ktmax >= 1) load_kv(1, 64);
    CP_COMMIT();                               // group: chunk1 (or empty)

    float o[16][4];
    float m_i[2] = {-1e30f, -1e30f};
    float l_i[2] = {0.f, 0.f};
#pragma unroll
    for (int nt = 0; nt < 16; ++nt)
#pragma unroll
        for (int e = 0; e < 4; ++e) o[nt][e] = 0.f;

    const float scale = 0.08838834764831845f;   // 1/sqrt(128)
    const int r0g = m0 + wm + gid;

    for (int kt = 0; kt <= ktmax; ++kt) {
        const int n0 = kt << 6;
        CP_WAIT(1);                 // chunk kt (and Q) resident
        __syncthreads();

        const uint32_t st  = sKV + (kt & 1) * KV_STAGE_B;
        const uint32_t sKh = st, sKl = st + KV_TILE_B;
        const uint32_t sVh = st + 2 * KV_TILE_B, sVl = st + 3 * KV_TILE_B;

        if (m0 + wm + 15 >= n0) {   // warp has unmasked rows in this chunk
            // ---- S = Q K^T (bf16x3) ----
            float s[8][4];
#pragma unroll
            for (int nt = 0; nt < 8; ++nt)
#pragma unroll
                for (int e = 0; e < 4; ++e) s[nt][e] = 0.f;

#pragma unroll
            for (int ks = 0; ks < 8; ++ks) {
                const int jg = ks * 2 + lk;
                const int arow = wm + lrow8;
                uint32_t aoff = arow * 256 + ((jg ^ (arow & 7)) << 4);
                uint32_t qfh[4], qfl[4];
                ldsm4(qfh, sQh + aoff);
                ldsm4(qfl, sQl + aoff);
#pragma unroll
                for (int g = 0; g < 4; ++g) {
                    const int brow = g * 16 + lrow8;
                    uint32_t boff = brow * 256 + ((jg ^ (brow & 7)) << 4);
                    uint32_t kh[4], klf[4];
                    ldsm4(kh,  sKh + boff);
                    ldsm4(klf, sKl + boff);
                    mma16816(s[2 * g],     qfh, kh[0],  kh[2]);
                    mma16816(s[2 * g],     qfl, kh[0],  kh[2]);
                    mma16816(s[2 * g],     qfh, klf[0], klf[2]);
                    mma16816(s[2 * g + 1], qfh, kh[1],  kh[3]);
                    mma16816(s[2 * g + 1], qfl, kh[1],  kh[3]);
                    mma16816(s[2 * g + 1], qfh, klf[1], klf[3]);
                }
            }

            // scale + causal mask
            const bool diag = (n0 + 63 > m0 + wm);
#pragma unroll
            for (int nt = 0; nt < 8; ++nt) {
                const int c0 = n0 + nt * 8 + tig * 2;
#pragma unroll
                for (int e = 0; e < 4; ++e) s[nt][e] *= scale;
                if (diag) {
                    if (c0     > r0g)     s[nt][0] = -1e30f;
                    if (c0 + 1 > r0g)     s[nt][1] = -1e30f;
                    if (c0     > r0g + 8) s[nt][2] = -1e30f;
                    if (c0 + 1 > r0g + 8) s[nt][3] = -1e30f;
                }
            }

            // ---- online softmax ----
#pragma unroll
            for (int rr = 0; rr < 2; ++rr) {
                float mx = -1e30f;
#pragma unroll
                for (int nt = 0; nt < 8; ++nt)
                    mx = fmaxf(mx, fmaxf(s[nt][2 * rr], s[nt][2 * rr + 1]));
                mx = fmaxf(mx, __shfl_xor_sync(0xffffffffu, mx, 1));
                mx = fmaxf(mx, __shfl_xor_sync(0xffffffffu, mx, 2));
                float m_new = fmaxf(m_i[rr], mx);
                float alpha = __expf(m_i[rr] - m_new);
                float sum = 0.f;
#pragma unroll
                for (int nt = 0; nt < 8; ++nt) {
                    float p0 = __expf(s[nt][2 * rr]     - m_new);
                    float p1 = __expf(s[nt][2 * rr + 1] - m_new);
                    s[nt][2 * rr]     = p0;
                    s[nt][2 * rr + 1] = p1;
                    sum += p0 + p1;
                }
                sum += __shfl_xor_sync(0xffffffffu, sum, 1);
                sum += __shfl_xor_sync(0xffffffffu, sum, 2);
                l_i[rr] = l_i[rr] * alpha + sum;
                m_i[rr] = m_new;
#pragma unroll
                for (int nt = 0; nt < 16; ++nt) {
                    o[nt][2 * rr]     *= alpha;
                    o[nt][2 * rr + 1] *= alpha;
                }
            }

            // ---- O += P V (bf16x3) ----
#pragma unroll
            for (int j = 0; j < 4; ++j) {
                uint32_t ah[4], al[4];
#pragma unroll
                for (int half = 0; half < 2; ++half) {
                    const float* sp = s[2 * j + half];
#pragma unroll
                    for (int rr = 0; rr < 2; ++rr) {
                        float p0 = sp[2 * rr], p1 = sp[2 * rr + 1];
                        uint32_t pk = pack_bf16(p0, p1);
                        float b0 = __uint_as_float(pk << 16);
                        float b1 = __uint_as_float(pk & 0xFFFF0000u);
                        ah[half * 2 + rr] = pk;
                        al[half * 2 + rr] = pack_bf16(p0 - b0, p1 - b1);
                    }
                }
                const int vrow = j * 16 + lrow8;
#pragma unroll
                for (int g = 0; g < 8; ++g) {
                    const int jj = g * 2 + lk;
                    uint32_t voff = vrow * 256 + ((jj ^ (vrow & 7)) << 4);
                    uint32_t vh[4], vl[4];
                    ldsm4t(vh, sVh + voff);
                    ldsm4t(vl, sVl + voff);
                    mma16816(o[2 * g],     ah, vh[0], vh[1]);
                    mma16816(o[2 * g],     al, vh[0], vh[1]);
                    mma16816(o[2 * g],     ah, vl[0], vl[1]);
                    mma16816(o[2 * g + 1], ah, vh[2], vh[3]);
                    mma16816(o[2 * g + 1], al, vh[2], vh[3]);
                    mma16816(o[2 * g + 1], ah, vl[2], vl[3]);
                }
            }
        }

        __syncthreads();            // all warps done reading stage kt&1
        if (kt + 2 <= ktmax) load_kv(kt & 1, (kt + 2) << 6);
        CP_COMMIT();                // always commit (possibly empty)
    }

    // ---- epilogue: normalize, split to bf16 h/l, write ----
    const float inv0 = 1.0f / l_i[0];
    const float inv1 = 1.0f / l_i[1];
    const size_t ybase = (size_t)b * Sdim * Cdim + (size_t)h * Ddim;
    __nv_bfloat16* yh = g_yh + ybase;
    __nv_bfloat16* yl = g_yl + ybase;
    const size_t row0 = (size_t)(m0 + wm + gid) * Cdim;
    const size_t row1 = row0 + 8 * Cdim;
#pragma unroll
    for (int nt = 0; nt < 16; ++nt) {
        const int col = nt * 8 + tig * 2;
        float p0 = o[nt][0] * inv0, p1 = o[nt][1] * inv0;
        uint32_t pk = pack_bf16(p0, p1);
        float b0 = __uint_as_float(pk << 16);
        float b1 = __uint_as_float(pk & 0xFFFF0000u);
        *(uint32_t*)(yh + row0 + col) = pk;
        *(uint32_t*)(yl + row0 + col) = pack_bf16(p0 - b0, p1 - b1);
        p0 = o[nt][2] * inv1; p1 = o[nt][3] * inv1;
        pk = pack_bf16(p0, p1);
        b0 = __uint_as_float(pk << 16);
        b1 = __uint_as_float(pk & 0xFFFF0000u);
        *(uint32_t*)(yh + row1 + col) = pk;
        *(uint32_t*)(yl + row1 + col) = pack_bf16(p0 - b0, p1 - b1);
    }
}

// ---------------------------------------------------------------------------
// Launch
// ---------------------------------------------------------------------------
extern "C" void kernel_launch(void* const* d_in, const int* in_sizes, int n_in,
                              void* d_out, int out_size)
{
    const float* x      = (const float*)d_in[0];
    const float* w_qkv  = (const float*)d_in[1];
    const float* b_qkv  = (const float*)d_in[2];
    const float* w_proj = (const float*)d_in[3];
    const float* b_proj = (const float*)d_in[4];
    float* out = (float*)d_out;

    __nv_bfloat16 *qkvh, *qkvl, *xh, *xl, *yh, *yl, *wqh, *wql, *wph, *wpl;
    cudaGetSymbolAddress((void**)&qkvh, g_qkvh);
    cudaGetSymbolAddress((void**)&qkvl, g_qkvl);
    cudaGetSymbolAddress((void**)&xh,  g_xh);
    cudaGetSymbolAddress((void**)&xl,  g_xl);
    cudaGetSymbolAddress((void**)&yh,  g_yh);
    cudaGetSymbolAddress((void**)&yl,  g_yl);
    cudaGetSymbolAddress((void**)&wqh, g_wqkvT_h);
    cudaGetSymbolAddress((void**)&wql, g_wqkvT_l);
    cudaGetSymbolAddress((void**)&wph, g_wprojT_h);
    cudaGetSymbolAddress((void**)&wpl, g_wprojT_l);

    cudaFuncSetAttribute(gemm_mma_kernel<0>,
                         cudaFuncAttributeMaxDynamicSharedMemorySize, GEMM_SMEM);
    cudaFuncSetAttribute(gemm_mma_kernel<1>,
                         cudaFuncAttributeMaxDynamicSharedMemorySize, GEMM_SMEM);
    cudaFuncSetAttribute(attn_mma_kernel,
                         cudaFuncAttributeMaxDynamicSharedMemorySize, ATTN_SMEM);

    // 1) splits
    {
        int n = Mtok * Cdim;
        split_kernel<<<(n / 4 + 255) / 256, 256>>>(x, xh, xl, n);
    }
    transpose_split_kernel<<<dim3(QKV_N / 32, Cdim / 32), dim3(32, 8)>>>(
        w_qkv, wqh, wql, Cdim, QKV_N);
    transpose_split_kernel<<<dim3(Cdim / 32, Cdim / 32), dim3(32, 8)>>>(
        w_proj, wph, wpl, Cdim, Cdim);

    // 2) qkv = x @ w_qkv + b_qkv   [8192, 6144] -> split bf16 h/l
    gemm_mma_kernel<1><<<dim3(QKV_N / 128, Mtok / 128), 256, GEMM_SMEM>>>(
        xh, xl, wqh, wql, b_qkv, nullptr, qkvh, qkvl, Mtok, QKV_N, Cdim);

    // 3) flash attention (mma, cp.async pipelined) -> yh/yl bf16
    {
        dim3 grid(Sdim / 128, Hdim, Bdim);
        attn_mma_kernel<<<grid, 256, ATTN_SMEM>>>();
    }

    // 4) out = y @ w_proj + b_proj   [8192, 2048] fp32
    gemm_mma_kernel<0><<<dim3(Cdim / 128, Mtok / 128), 256, GEMM_SMEM>>>(
        yh, yl, wph, wpl, b_proj, out, nullptr, nullptr, Mtok, Cdim, Cdim);
}

// round 6
// speedup vs baseline: 3.4492x; 1.3229x over previous
#include <cuda_runtime.h>
#include <cuda_fp16.h>
#include <cstdint>

// Problem constants
#define Cdim 2048
#define Sdim 2048
#define Bdim 4
#define Hdim 16
#define Ddim 128
#define Mtok (Bdim * Sdim)          // 8192
#define QKV_N (3 * Cdim)            // 6144

// ---------------------------------------------------------------------------
// Scratch (device globals — no allocation allowed)
// ---------------------------------------------------------------------------
__device__ __half g_qkvh[(size_t)Mtok * QKV_N];      // qkv hi (fp16)
__device__ __half g_qkvl[(size_t)Mtok * QKV_N];      // qkv lo (fp16)
__device__ __half g_xh[(size_t)Mtok * Cdim];
__device__ __half g_xl[(size_t)Mtok * Cdim];
__device__ __half g_yh[(size_t)Mtok * Cdim];
__device__ __half g_yl[(size_t)Mtok * Cdim];
__device__ __half g_wqkvT[(size_t)QKV_N * Cdim];     // [6144, 2048] (N,K) fp16
__device__ __half g_wprojT[(size_t)Cdim * Cdim];     // [2048, 2048] fp16

// ---------------------------------------------------------------------------
// PTX helpers (base-ISA only: cp.async / ldmatrix / mma.sync)
// ---------------------------------------------------------------------------
__device__ __forceinline__ uint32_t smem_u32(const void* p) {
    uint32_t a;
    asm("{ .reg .u64 t; cvta.to.shared.u64 t, %1; cvt.u32.u64 %0, t; }" : "=r"(a) : "l"(p));
    return a;
}

#define CP_ASYNC16(dst, src) \
    asm volatile("cp.async.cg.shared.global [%0], [%1], 16;" :: "r"(dst), "l"(src))
#define CP_COMMIT() asm volatile("cp.async.commit_group;" ::: "memory")
#define CP_WAIT(n)  asm volatile("cp.async.wait_group %0;" :: "n"(n) : "memory")

__device__ __forceinline__ void ldsm4(uint32_t* r, uint32_t addr) {
    asm volatile("ldmatrix.sync.aligned.m8n8.x4.shared.b16 {%0,%1,%2,%3}, [%4];"
                 : "=r"(r[0]), "=r"(r[1]), "=r"(r[2]), "=r"(r[3]) : "r"(addr));
}
__device__ __forceinline__ void ldsm4t(uint32_t* r, uint32_t addr) {
    asm volatile("ldmatrix.sync.aligned.m8n8.x4.trans.shared.b16 {%0,%1,%2,%3}, [%4];"
                 : "=r"(r[0]), "=r"(r[1]), "=r"(r[2]), "=r"(r[3]) : "r"(addr));
}

// fp16 MMA, fp32 accumulate
__device__ __forceinline__ void mma16816(float* d, const uint32_t* a,
                                         uint32_t b0, uint32_t b1) {
    asm volatile(
        "mma.sync.aligned.m16n8k16.row.col.f32.f16.f16.f32 "
        "{%0,%1,%2,%3}, {%4,%5,%6,%7}, {%8,%9}, {%0,%1,%2,%3};"
        : "+f"(d[0]), "+f"(d[1]), "+f"(d[2]), "+f"(d[3])
        : "r"(a[0]), "r"(a[1]), "r"(a[2]), "r"(a[3]), "r"(b0), "r"(b1));
}

// pack two fp32 -> fp16x2 (first arg in low half)
__device__ __forceinline__ uint32_t pack_f16(float lo, float hi) {
    uint32_t r;
    asm("cvt.rn.f16x2.f32 %0, %1, %2;" : "=r"(r) : "f"(hi), "f"(lo));
    return r;
}
__device__ __forceinline__ float2 unpack_f16(uint32_t pk) {
    __half2 h = *reinterpret_cast<__half2*>(&pk);
    return make_float2(__low2float(h), __high2float(h));
}

// ---------------------------------------------------------------------------
// Conversion kernels
// ---------------------------------------------------------------------------
__global__ void split_kernel(const float* __restrict__ in,
                             __half* __restrict__ hi,
                             __half* __restrict__ lo, int n)
{
    int i = (blockIdx.x * blockDim.x + threadIdx.x) * 4;
    if (i >= n) return;
    float4 v = *(const float4*)(in + i);
    float vv[4] = {v.x, v.y, v.z, v.w};
    uint32_t hp[2], lp[2];
#pragma unroll
    for (int p = 0; p < 2; ++p) {
        uint32_t pk = pack_f16(vv[2 * p], vv[2 * p + 1]);
        float2 r = unpack_f16(pk);
        hp[p] = pk;
        lp[p] = pack_f16(vv[2 * p] - r.x, vv[2 * p + 1] - r.y);
    }
    *(uint2*)(hi + i) = make_uint2(hp[0], hp[1]);
    *(uint2*)(lo + i) = make_uint2(lp[0], lp[1]);
}

// W [K, N] fp32 -> Wt [N, K] fp16 (single-term B side)
__global__ void transpose_h_kernel(const float* __restrict__ W,
                                   __half* __restrict__ Th, int K, int N)
{
    __shared__ float tile[32][33];
    int n0 = blockIdx.x * 32, k0 = blockIdx.y * 32;
    int tx = threadIdx.x, ty = threadIdx.y;   // 32 x 8
#pragma unroll
    for (int j = 0; j < 32; j += 8)
        tile[ty + j][tx] = W[(size_t)(k0 + ty + j) * N + n0 + tx];
    __syncthreads();
#pragma unroll
    for (int j = 0; j < 32; j += 8)
        Th[(size_t)(n0 + ty + j) * K + k0 + tx] = __float2half(tile[tx][ty + j]);
}

// ---------------------------------------------------------------------------
// fp16x2 GEMM: C[M,N] = (Ah+Al) @ Bh^T + bias. Tile 128x64, BK=32, 4-stage
// cp.async pipeline, 2 CTAs/SM. 8 warps (4m x 2n), warp tile 32x32.
// OUTM=0: fp32 C.  OUTM=1: split fp16 (Ch, Cl).
// ---------------------------------------------------------------------------
#define GA_TILE 8192                       // 128 x 32 fp16
#define GB_TILE 4096                       // 64 x 32 fp16
#define GSTAGE (2 * GA_TILE + GB_TILE)     // 20480
#define GEMM_SMEM (4 * GSTAGE)             // 81920

template<int OUTM>
__global__ __launch_bounds__(256, 2) void gemm_mma_kernel(
    const __half* __restrict__ Ah, const __half* __restrict__ Al,
    const __half* __restrict__ Bh,
    const float* __restrict__ bias, float* __restrict__ C,
    __half* __restrict__ Ch, __half* __restrict__ Cl,
    int M, int N, int K)
{
    extern __shared__ char smem[];
    const uint32_t sbase = smem_u32(smem);

    const int t   = threadIdx.x;
    const int wid = t >> 5;
    const int lid = t & 31;
    const int n0  = blockIdx.x * 64;
    const int m0  = blockIdx.y * 128;
    const int wm  = (wid & 3) * 32;
    const int wn  = (wid >> 2) * 32;

    const __half* gA[2] = { Ah + (size_t)m0 * K, Al + (size_t)m0 * K };
    const __half* gB    = Bh + (size_t)n0 * K;

    float acc[2][4][4];
#pragma unroll
    for (int mt = 0; mt < 2; ++mt)
#pragma unroll
        for (int nt = 0; nt < 4; ++nt)
#pragma unroll
            for (int e = 0; e < 4; ++e) acc[mt][nt][e] = 0.f;

    auto load_stage = [&](int stage, int k0) {
        uint32_t sb = sbase + stage * GSTAGE;
        // A: 1024 segments (2 tiles x 128 rows x 4), B: 256 segments
#pragma unroll
        for (int i = 0; i < 4; ++i) {
            int idx = t + i * 256;          // < 1024
            int tl  = idx >> 9;
            int rem = idx & 511;
            int row = rem >> 2, j = rem & 3;
            const void* src = gA[tl] + (size_t)row * K + k0 + j * 8;
            uint32_t dst = sb + tl * GA_TILE + row * 64 + (((j ^ ((row >> 1) & 3))) << 4);
            CP_ASYNC16(dst, src);
        }
        {
            int rem = t;                    // 0..255
            int row = rem >> 2, j = rem & 3;
            const void* src = gB + (size_t)row * K + k0 + j * 8;
            uint32_t dst = sb + 2 * GA_TILE + row * 64 + (((j ^ ((row >> 1) & 3))) << 4);
            CP_ASYNC16(dst, src);
        }
    };

    const int lrow8 = (lid & 7) + ((lid >> 3) & 1) * 8;
    const int lk    = (lid >> 4) & 1;

    const int nk = K / 32;                  // 64 chunks
    load_stage(0, 0);  CP_COMMIT();
    load_stage(1, 32); CP_COMMIT();
    load_stage(2, 64); CP_COMMIT();

    for (int c = 0; c < nk; ++c) {
        CP_WAIT(2);                 // chunk c resident
        __syncthreads();            // all warps done with stage (c+3)%4's old data
        if (c + 3 < nk) load_stage((c + 3) & 3, (c + 3) * 32);
        CP_COMMIT();

        const uint32_t sb = sbase + (c & 3) * GSTAGE;
        const uint32_t aH = sb, aL = sb + GA_TILE, bH = sb + 2 * GA_TILE;

#pragma unroll
        for (int k16 = 0; k16 < 2; ++k16) {
            const int jg = k16 * 2 + lk;

            uint32_t bh[8];
#pragma unroll
            for (int nb = 0; nb < 2; ++nb) {
                int row = wn + nb * 16 + lrow8;
                uint32_t off = row * 64 + (((jg ^ ((row >> 1) & 3))) << 4);
                ldsm4(&bh[nb * 4], bH + off);
            }
#pragma unroll
            for (int mt = 0; mt < 2; ++mt) {
                int row = wm + mt * 16 + lrow8;
                uint32_t off = row * 64 + (((jg ^ ((row >> 1) & 3))) << 4);
                uint32_t ah[4], al[4];
                ldsm4(ah, aH + off);
                ldsm4(al, aL + off);
#pragma unroll
                for (int nb = 0; nb < 2; ++nb) {
                    mma16816(acc[mt][2 * nb],     ah, bh[nb * 4 + 0], bh[nb * 4 + 2]);
                    mma16816(acc[mt][2 * nb],     al, bh[nb * 4 + 0], bh[nb * 4 + 2]);
                    mma16816(acc[mt][2 * nb + 1], ah, bh[nb * 4 + 1], bh[nb * 4 + 3]);
                    mma16816(acc[mt][2 * nb + 1], al, bh[nb * 4 + 1], bh[nb * 4 + 3]);
                }
            }
        }
    }

    const int gid = lid >> 2;
    const int tig = lid & 3;
#pragma unroll
    for (int mt = 0; mt < 2; ++mt) {
        int m = m0 + wm + mt * 16 + gid;
#pragma unroll
        for (int nt = 0; nt < 4; ++nt) {
            int n = n0 + wn + nt * 8 + tig * 2;
            float b0 = bias[n], b1 = bias[n + 1];
            float v00 = acc[mt][nt][0] + b0, v01 = acc[mt][nt][1] + b1;
            float v10 = acc[mt][nt][2] + b0, v11 = acc[mt][nt][3] + b1;
            if (OUTM == 0) {
                *(float2*)(C + (size_t)m * N + n)       = make_float2(v00, v01);
                *(float2*)(C + (size_t)(m + 8) * N + n) = make_float2(v10, v11);
            } else {
                uint32_t pk = pack_f16(v00, v01);
                float2 r = unpack_f16(pk);
                *(uint32_t*)(Ch + (size_t)m * N + n) = pk;
                *(uint32_t*)(Cl + (size_t)m * N + n) = pack_f16(v00 - r.x, v01 - r.y);
                pk = pack_f16(v10, v11);
                r = unpack_f16(pk);
                *(uint32_t*)(Ch + (size_t)(m + 8) * N + n) = pk;
                *(uint32_t*)(Cl + (size_t)(m + 8) * N + n) = pack_f16(v10 - r.x, v11 - r.y);
            }
        }
    }
}

// ---------------------------------------------------------------------------
// Flash attention, fp16x2 (Q split hi/lo; K,V single fp16), causal.
// CTA: 128 q-rows x 64-kv chunks. 8 warps x 16 q-rows.
// Smem: Q h/l (64 KB) + 2-stage {Kh,Vh} (2 x 32 KB) = 128 KB.
// ---------------------------------------------------------------------------
#define KV_TILE_B 16384                     // 64 rows x 256 B
#define KV_STAGE_B (2 * KV_TILE_B)          // Kh, Vh
#define Q_TILE_B   32768                    // 128 rows x 256 B
#define ATTN_SMEM (2 * Q_TILE_B + 2 * KV_STAGE_B)   // 131072

__global__ __launch_bounds__(256) void attn_mma_kernel()
{
    extern __shared__ char sm8[];
    const uint32_t sb  = smem_u32(sm8);
    const uint32_t sQh = sb, sQl = sb + Q_TILE_B;
    const uint32_t sKV = sb + 2 * Q_TILE_B;

    const int t   = threadIdx.x;
    const int wid = t >> 5;
    const int lid = t & 31;
    const int qt  = blockIdx.x;
    const int h   = blockIdx.y;
    const int b   = blockIdx.z;
    const int m0  = qt * 128;
    const int wm  = wid * 16;
    const int gid = lid >> 2;
    const int tig = lid & 3;
    const int lrow8 = (lid & 7) + ((lid >> 3) & 1) * 8;
    const int lk    = (lid >> 4) & 1;

    const size_t tok0 = ((size_t)b * Sdim + m0) * QKV_N;
    const __half* qh = g_qkvh + tok0 + h * Ddim;
    const __half* ql = g_qkvl + tok0 + h * Ddim;
    const size_t kvtok = (size_t)b * Sdim * QKV_N;
    const __half* kv_base[2] = {
        g_qkvh + kvtok + Cdim + h * Ddim,      // Kh
        g_qkvh + kvtok + 2 * Cdim + h * Ddim   // Vh
    };

    auto load_kv = [&](int stage, int n0) {
        uint32_t dstb = sKV + stage * KV_STAGE_B;
#pragma unroll
        for (int i = 0; i < 8; ++i) {
            int idx  = t + i * 256;            // 0..2047
            int tile = idx >> 10;
            int rem  = idx & 1023;
            int row  = rem >> 4, j = rem & 15;
            const void* src = kv_base[tile] + (size_t)(n0 + row) * QKV_N + j * 8;
            uint32_t dst = dstb + tile * KV_TILE_B + row * 256 + ((j ^ (row & 7)) << 4);
            CP_ASYNC16(dst, src);
        }
    };

    // Q tile loads (group 0, with chunk 0)
#pragma unroll
    for (int i = 0; i < 16; ++i) {
        int idx  = t + i * 256;                // 0..4095
        int tile = idx >> 11;                  // 0: Qh, 1: Ql
        int rem  = idx & 2047;
        int row  = rem >> 4, j = rem & 15;
        const __half* src = (tile == 0 ? qh : ql) + (size_t)row * QKV_N + j * 8;
        uint32_t dst = (tile == 0 ? sQh : sQl) + row * 256 + ((j ^ (row & 7)) << 4);
        CP_ASYNC16(dst, src);
    }
    load_kv(0, 0);
    CP_COMMIT();
    const int ktmax = (m0 >> 6) + 1;
    if (ktmax >= 1) load_kv(1, 64);
    CP_COMMIT();

    float o[16][4];
    float m_i[2] = {-1e30f, -1e30f};
    float l_i[2] = {0.f, 0.f};
#pragma unroll
    for (int nt = 0; nt < 16; ++nt)
#pragma unroll
        for (int e = 0; e < 4; ++e) o[nt][e] = 0.f;

    const float scale = 0.08838834764831845f;   // 1/sqrt(128)
    const int r0g = m0 + wm + gid;

    for (int kt = 0; kt <= ktmax; ++kt) {
        const int n0 = kt << 6;
        CP_WAIT(1);
        __syncthreads();

        const uint32_t st  = sKV + (kt & 1) * KV_STAGE_B;
        const uint32_t sKh = st, sVh = st + KV_TILE_B;

        if (m0 + wm + 15 >= n0) {
            // ---- S = (Qh+Ql) Kh^T ----
            float s[8][4];
#pragma unroll
            for (int nt = 0; nt < 8; ++nt)
#pragma unroll
                for (int e = 0; e < 4; ++e) s[nt][e] = 0.f;

#pragma unroll
            for (int ks = 0; ks < 8; ++ks) {
                const int jg = ks * 2 + lk;
                const int arow = wm + lrow8;
                uint32_t aoff = arow * 256 + ((jg ^ (arow & 7)) << 4);
                uint32_t qfh[4], qfl[4];
                ldsm4(qfh, sQh + aoff);
                ldsm4(qfl, sQl + aoff);
#pragma unroll
                for (int g = 0; g < 4; ++g) {
                    const int brow = g * 16 + lrow8;
                    uint32_t boff = brow * 256 + ((jg ^ (brow & 7)) << 4);
                    uint32_t kh[4];
                    ldsm4(kh, sKh + boff);
                    mma16816(s[2 * g],     qfh, kh[0], kh[2]);
                    mma16816(s[2 * g],     qfl, kh[0], kh[2]);
                    mma16816(s[2 * g + 1], qfh, kh[1], kh[3]);
                    mma16816(s[2 * g + 1], qfl, kh[1], kh[3]);
                }
            }

            // scale + causal mask
            const bool diag = (n0 + 63 > m0 + wm);
#pragma unroll
            for (int nt = 0; nt < 8; ++nt) {
                const int c0 = n0 + nt * 8 + tig * 2;
#pragma unroll
                for (int e = 0; e < 4; ++e) s[nt][e] *= scale;
                if (diag) {
                    if (c0     > r0g)     s[nt][0] = -1e30f;
                    if (c0 + 1 > r0g)     s[nt][1] = -1e30f;
                    if (c0     > r0g + 8) s[nt][2] = -1e30f;
                    if (c0 + 1 > r0g + 8) s[nt][3] = -1e30f;
                }
            }

            // ---- online softmax ----
#pragma unroll
            for (int rr = 0; rr < 2; ++rr) {
                float mx = -1e30f;
#pragma unroll
                for (int nt = 0; nt < 8; ++nt)
                    mx = fmaxf(mx, fmaxf(s[nt][2 * rr], s[nt][2 * rr + 1]));
                mx = fmaxf(mx, __shfl_xor_sync(0xffffffffu, mx, 1));
                mx = fmaxf(mx, __shfl_xor_sync(0xffffffffu, mx, 2));
                float m_new = fmaxf(m_i[rr], mx);
                float alpha = __expf(m_i[rr] - m_new);
                float sum = 0.f;
#pragma unroll
                for (int nt = 0; nt < 8; ++nt) {
                    float p0 = __expf(s[nt][2 * rr]     - m_new);
                    float p1 = __expf(s[nt][2 * rr + 1] - m_new);
                    s[nt][2 * rr]     = p0;
                    s[nt][2 * rr + 1] = p1;
                    sum += p0 + p1;
                }
                sum += __shfl_xor_sync(0xffffffffu, sum, 1);
                sum += __shfl_xor_sync(0xffffffffu, sum, 2);
                l_i[rr] = l_i[rr] * alpha + sum;
                m_i[rr] = m_new;
#pragma unroll
                for (int nt = 0; nt < 16; ++nt) {
                    o[nt][2 * rr]     *= alpha;
                    o[nt][2 * rr + 1] *= alpha;
                }
            }

            // ---- O += (Ph+Pl) Vh ----
#pragma unroll
            for (int j = 0; j < 4; ++j) {
                uint32_t ah[4], al[4];
#pragma unroll
                for (int half = 0; half < 2; ++half) {
                    const float* sp = s[2 * j + half];
#pragma unroll
                    for (int rr = 0; rr < 2; ++rr) {
                        float p0 = sp[2 * rr], p1 = sp[2 * rr + 1];
                        uint32_t pk = pack_f16(p0, p1);
                        float2 r = unpack_f16(pk);
                        ah[half * 2 + rr] = pk;
                        al[half * 2 + rr] = pack_f16(p0 - r.x, p1 - r.y);
                    }
                }
                const int vrow = j * 16 + lrow8;
#pragma unroll
                for (int g = 0; g < 8; ++g) {
                    const int jj = g * 2 + lk;
                    uint32_t voff = vrow * 256 + ((jj ^ (vrow & 7)) << 4);
                    uint32_t vh[4];
                    ldsm4t(vh, sVh + voff);
                    mma16816(o[2 * g],     ah, vh[0], vh[1]);
                    mma16816(o[2 * g],     al, vh[0], vh[1]);
                    mma16816(o[2 * g + 1], ah, vh[2], vh[3]);
                    mma16816(o[2 * g + 1], al, vh[2], vh[3]);
                }
            }
        }

        __syncthreads();
        if (kt + 2 <= ktmax) load_kv(kt & 1, (kt + 2) << 6);
        CP_COMMIT();
    }

    // ---- epilogue: normalize, split to fp16 h/l, write ----
    const float inv0 = 1.0f / l_i[0];
    const float inv1 = 1.0f / l_i[1];
    const size_t ybase = (size_t)b * Sdim * Cdim + (size_t)h * Ddim;
    __half* yh = g_yh + ybase;
    __half* yl = g_yl + ybase;
    const size_t row0 = (size_t)(m0 + wm + gid) * Cdim;
    const size_t row1 = row0 + 8 * Cdim;
#pragma unroll
    for (int nt = 0; nt < 16; ++nt) {
        const int col = nt * 8 + tig * 2;
        float p0 = o[nt][0] * inv0, p1 = o[nt][1] * inv0;
        uint32_t pk = pack_f16(p0, p1);
        float2 r = unpack_f16(pk);
        *(uint32_t*)(yh + row0 + col) = pk;
        *(uint32_t*)(yl + row0 + col) = pack_f16(p0 - r.x, p1 - r.y);
        p0 = o[nt][2] * inv1; p1 = o[nt][3] * inv1;
        pk = pack_f16(p0, p1);
        r = unpack_f16(pk);
        *(uint32_t*)(yh + row1 + col) = pk;
        *(uint32_t*)(yl + row1 + col) = pack_f16(p0 - r.x, p1 - r.y);
    }
}

// ---------------------------------------------------------------------------
// Launch
// ---------------------------------------------------------------------------
extern "C" void kernel_launch(void* const* d_in, const int* in_sizes, int n_in,
                              void* d_out, int out_size)
{
    const float* x      = (const float*)d_in[0];
    const float* w_qkv  = (const float*)d_in[1];
    const float* b_qkv  = (const float*)d_in[2];
    const float* w_proj = (const float*)d_in[3];
    const float* b_proj = (const float*)d_in[4];
    float* out = (float*)d_out;

    __half *qkvh, *qkvl, *xh, *xl, *yh, *yl, *wq, *wp;
    cudaGetSymbolAddress((void**)&qkvh, g_qkvh);
    cudaGetSymbolAddress((void**)&qkvl, g_qkvl);
    cudaGetSymbolAddress((void**)&xh,  g_xh);
    cudaGetSymbolAddress((void**)&xl,  g_xl);
    cudaGetSymbolAddress((void**)&yh,  g_yh);
    cudaGetSymbolAddress((void**)&yl,  g_yl);
    cudaGetSymbolAddress((void**)&wq,  g_wqkvT);
    cudaGetSymbolAddress((void**)&wp,  g_wprojT);

    cudaFuncSetAttribute(gemm_mma_kernel<0>,
                         cudaFuncAttributeMaxDynamicSharedMemorySize, GEMM_SMEM);
    cudaFuncSetAttribute(gemm_mma_kernel<1>,
                         cudaFuncAttributeMaxDynamicSharedMemorySize, GEMM_SMEM);
    cudaFuncSetAttribute(attn_mma_kernel,
                         cudaFuncAttributeMaxDynamicSharedMemorySize, ATTN_SMEM);

    // 1) input splits / weight transposes (fp16)
    {
        int n = Mtok * Cdim;
        split_kernel<<<(n / 4 + 255) / 256, 256>>>(x, xh, xl, n);
    }
    transpose_h_kernel<<<dim3(QKV_N / 32, Cdim / 32), dim3(32, 8)>>>(
        w_qkv, wq, Cdim, QKV_N);
    transpose_h_kernel<<<dim3(Cdim / 32, Cdim / 32), dim3(32, 8)>>>(
        w_proj, wp, Cdim, Cdim);

    // 2) qkv = x @ w_qkv + b_qkv   [8192, 6144] -> split fp16 h/l
    gemm_mma_kernel<1><<<dim3(QKV_N / 64, Mtok / 128), 256, GEMM_SMEM>>>(
        xh, xl, wq, b_qkv, nullptr, qkvh, qkvl, Mtok, QKV_N, Cdim);

    // 3) flash attention -> yh/yl fp16
    {
        dim3 grid(Sdim / 128, Hdim, Bdim);
        attn_mma_kernel<<<grid, 256, ATTN_SMEM>>>();
    }

    // 4) out = y @ w_proj + b_proj   [8192, 2048] fp32
    gemm_mma_kernel<0><<<dim3(Cdim / 64, Mtok / 128), 256, GEMM_SMEM>>>(
        yh, yl, wp, b_proj, out, nullptr, nullptr, Mtok, Cdim, Cdim);
}

// round 7
// speedup vs baseline: 3.6320x; 1.0530x over previous
#include <cuda_runtime.h>
#include <cuda_fp16.h>
#include <cstdint>

// Problem constants
#define Cdim 2048
#define Sdim 2048
#define Bdim 4
#define Hdim 16
#define Ddim 128
#define Mtok (Bdim * Sdim)          // 8192
#define QKV_N (3 * Cdim)            // 6144

// ---------------------------------------------------------------------------
// Scratch (device globals — no allocation allowed)
// ---------------------------------------------------------------------------
__device__ __half g_qkvh[(size_t)Mtok * QKV_N];      // qkv hi (fp16)
__device__ __half g_qkvl[(size_t)Mtok * QKV_N];      // qkv lo (fp16)
__device__ __half g_xh[(size_t)Mtok * Cdim];
__device__ __half g_xl[(size_t)Mtok * Cdim];
__device__ __half g_yh[(size_t)Mtok * Cdim];
__device__ __half g_yl[(size_t)Mtok * Cdim];
__device__ __half g_wqkvT[(size_t)QKV_N * Cdim];     // [6144, 2048] (N,K) fp16
__device__ __half g_wprojT[(size_t)Cdim * Cdim];     // [2048, 2048] fp16

// ---------------------------------------------------------------------------
// PTX helpers (base-ISA only: cp.async / ldmatrix / mma.sync)
// ---------------------------------------------------------------------------
__device__ __forceinline__ uint32_t smem_u32(const void* p) {
    uint32_t a;
    asm("{ .reg .u64 t; cvta.to.shared.u64 t, %1; cvt.u32.u64 %0, t; }" : "=r"(a) : "l"(p));
    return a;
}

#define CP_ASYNC16(dst, src) \
    asm volatile("cp.async.cg.shared.global [%0], [%1], 16;" :: "r"(dst), "l"(src))
#define CP_COMMIT() asm volatile("cp.async.commit_group;" ::: "memory")
#define CP_WAIT(n)  asm volatile("cp.async.wait_group %0;" :: "n"(n) : "memory")

__device__ __forceinline__ void ldsm4(uint32_t* r, uint32_t addr) {
    asm volatile("ldmatrix.sync.aligned.m8n8.x4.shared.b16 {%0,%1,%2,%3}, [%4];"
                 : "=r"(r[0]), "=r"(r[1]), "=r"(r[2]), "=r"(r[3]) : "r"(addr));
}
__device__ __forceinline__ void ldsm4t(uint32_t* r, uint32_t addr) {
    asm volatile("ldmatrix.sync.aligned.m8n8.x4.trans.shared.b16 {%0,%1,%2,%3}, [%4];"
                 : "=r"(r[0]), "=r"(r[1]), "=r"(r[2]), "=r"(r[3]) : "r"(addr));
}

// fp16 MMA, fp32 accumulate
__device__ __forceinline__ void mma16816(float* d, const uint32_t* a,
                                         uint32_t b0, uint32_t b1) {
    asm volatile(
        "mma.sync.aligned.m16n8k16.row.col.f32.f16.f16.f32 "
        "{%0,%1,%2,%3}, {%4,%5,%6,%7}, {%8,%9}, {%0,%1,%2,%3};"
        : "+f"(d[0]), "+f"(d[1]), "+f"(d[2]), "+f"(d[3])
        : "r"(a[0]), "r"(a[1]), "r"(a[2]), "r"(a[3]), "r"(b0), "r"(b1));
}

// pack two fp32 -> fp16x2 (first arg in low half)
__device__ __forceinline__ uint32_t pack_f16(float lo, float hi) {
    uint32_t r;
    asm("cvt.rn.f16x2.f32 %0, %1, %2;" : "=r"(r) : "f"(hi), "f"(lo));
    return r;
}
__device__ __forceinline__ float2 unpack_f16(uint32_t pk) {
    __half2 h = *reinterpret_cast<__half2*>(&pk);
    return make_float2(__low2float(h), __high2float(h));
}

// ---------------------------------------------------------------------------
// Conversion kernels
// ---------------------------------------------------------------------------
__global__ void split_kernel(const float* __restrict__ in,
                             __half* __restrict__ hi,
                             __half* __restrict__ lo, int n)
{
    int i = (blockIdx.x * blockDim.x + threadIdx.x) * 4;
    if (i >= n) return;
    float4 v = *(const float4*)(in + i);
    float vv[4] = {v.x, v.y, v.z, v.w};
    uint32_t hp[2], lp[2];
#pragma unroll
    for (int p = 0; p < 2; ++p) {
        uint32_t pk = pack_f16(vv[2 * p], vv[2 * p + 1]);
        float2 r = unpack_f16(pk);
        hp[p] = pk;
        lp[p] = pack_f16(vv[2 * p] - r.x, vv[2 * p + 1] - r.y);
    }
    *(uint2*)(hi + i) = make_uint2(hp[0], hp[1]);
    *(uint2*)(lo + i) = make_uint2(lp[0], lp[1]);
}

// W [K, N] fp32 -> Wt [N, K] fp16 (single-term B side)
__global__ void transpose_h_kernel(const float* __restrict__ W,
                                   __half* __restrict__ Th, int K, int N)
{
    __shared__ float tile[32][33];
    int n0 = blockIdx.x * 32, k0 = blockIdx.y * 32;
    int tx = threadIdx.x, ty = threadIdx.y;   // 32 x 8
#pragma unroll
    for (int j = 0; j < 32; j += 8)
        tile[ty + j][tx] = W[(size_t)(k0 + ty + j) * N + n0 + tx];
    __syncthreads();
#pragma unroll
    for (int j = 0; j < 32; j += 8)
        Th[(size_t)(n0 + ty + j) * K + k0 + tx] = __float2half(tile[tx][ty + j]);
}

// ---------------------------------------------------------------------------
// fp16x2 GEMM: C[M,N] = (Ah+Al) @ Bh^T + bias. Tile 128x128, BK=32,
// 4-stage cp.async pipeline, 2 CTAs/SM. 8 warps (4m x 2n), warp tile 32x64.
// OUTM=0: fp32 C.  OUTM=1: split fp16 (Ch, Cl).
// ---------------------------------------------------------------------------
#define GA_TILE 8192                       // 128 x 32 fp16
#define GSTAGE (3 * GA_TILE)               // Ah, Al, B  = 24576
#define GEMM_SMEM (4 * GSTAGE)             // 98304

template<int OUTM>
__global__ __launch_bounds__(256, 2) void gemm_mma_kernel(
    const __half* __restrict__ Ah, const __half* __restrict__ Al,
    const __half* __restrict__ Bh,
    const float* __restrict__ bias, float* __restrict__ C,
    __half* __restrict__ Ch, __half* __restrict__ Cl,
    int M, int N, int K)
{
    extern __shared__ char smem[];
    const uint32_t sbase = smem_u32(smem);

    const int t   = threadIdx.x;
    const int wid = t >> 5;
    const int lid = t & 31;
    const int n0  = blockIdx.x * 128;
    const int m0  = blockIdx.y * 128;
    const int wm  = (wid & 3) * 32;        // warp m offset
    const int wn  = (wid >> 2) * 64;       // warp n offset

    const __half* gA[2] = { Ah + (size_t)m0 * K, Al + (size_t)m0 * K };
    const __half* gB    = Bh + (size_t)n0 * K;

    float acc[2][8][4];
#pragma unroll
    for (int mt = 0; mt < 2; ++mt)
#pragma unroll
        for (int nt = 0; nt < 8; ++nt)
#pragma unroll
            for (int e = 0; e < 4; ++e) acc[mt][nt][e] = 0.f;

    auto load_stage = [&](int stage, int k0) {
        uint32_t sb = sbase + stage * GSTAGE;
        // A: 1024 segments (2 tiles x 128 rows x 4), B: 512 segments
#pragma unroll
        for (int i = 0; i < 4; ++i) {
            int idx = t + i * 256;          // < 1024
            int tl  = idx >> 9;
            int rem = idx & 511;
            int row = rem >> 2, j = rem & 3;
            const void* src = gA[tl] + (size_t)row * K + k0 + j * 8;
            uint32_t dst = sb + tl * GA_TILE + row * 64 + ((j ^ ((row >> 1) & 3)) << 4);
            CP_ASYNC16(dst, src);
        }
#pragma unroll
        for (int i = 0; i < 2; ++i) {
            int idx = t + i * 256;          // < 512
            int row = idx >> 2, j = idx & 3;
            const void* src = gB + (size_t)row * K + k0 + j * 8;
            uint32_t dst = sb + 2 * GA_TILE + row * 64 + ((j ^ ((row >> 1) & 3)) << 4);
            CP_ASYNC16(dst, src);
        }
    };

    const int lrow8 = (lid & 7) + ((lid >> 3) & 1) * 8;
    const int lk    = (lid >> 4) & 1;

    const int nk = K / 32;                  // 64 chunks
    load_stage(0, 0);  CP_COMMIT();
    load_stage(1, 32); CP_COMMIT();
    load_stage(2, 64); CP_COMMIT();

    for (int c = 0; c < nk; ++c) {
        CP_WAIT(2);                 // chunk c resident
        __syncthreads();
        if (c + 3 < nk) load_stage((c + 3) & 3, (c + 3) * 32);
        CP_COMMIT();

        const uint32_t sb = sbase + (c & 3) * GSTAGE;
        const uint32_t aH = sb, aL = sb + GA_TILE, bH = sb + 2 * GA_TILE;

#pragma unroll
        for (int k16 = 0; k16 < 2; ++k16) {
            const int jg = k16 * 2 + lk;

            uint32_t bh[16];
#pragma unroll
            for (int nb = 0; nb < 4; ++nb) {
                int row = wn + nb * 16 + lrow8;
                uint32_t off = row * 64 + ((jg ^ ((row >> 1) & 3)) << 4);
                ldsm4(&bh[nb * 4], bH + off);
            }
#pragma unroll
            for (int mt = 0; mt < 2; ++mt) {
                int row = wm + mt * 16 + lrow8;
                uint32_t off = row * 64 + ((jg ^ ((row >> 1) & 3)) << 4);
                uint32_t ah[4], al[4];
                ldsm4(ah, aH + off);
                ldsm4(al, aL + off);
#pragma unroll
                for (int nb = 0; nb < 4; ++nb) {
                    mma16816(acc[mt][2 * nb],     ah, bh[nb * 4 + 0], bh[nb * 4 + 2]);
                    mma16816(acc[mt][2 * nb],     al, bh[nb * 4 + 0], bh[nb * 4 + 2]);
                    mma16816(acc[mt][2 * nb + 1], ah, bh[nb * 4 + 1], bh[nb * 4 + 3]);
                    mma16816(acc[mt][2 * nb + 1], al, bh[nb * 4 + 1], bh[nb * 4 + 3]);
                }
            }
        }
    }

    const int gid = lid >> 2;
    const int tig = lid & 3;
#pragma unroll
    for (int mt = 0; mt < 2; ++mt) {
        int m = m0 + wm + mt * 16 + gid;
#pragma unroll
        for (int nt = 0; nt < 8; ++nt) {
            int n = n0 + wn + nt * 8 + tig * 2;
            float b0 = bias[n], b1 = bias[n + 1];
            float v00 = acc[mt][nt][0] + b0, v01 = acc[mt][nt][1] + b1;
            float v10 = acc[mt][nt][2] + b0, v11 = acc[mt][nt][3] + b1;
            if (OUTM == 0) {
                *(float2*)(C + (size_t)m * N + n)       = make_float2(v00, v01);
                *(float2*)(C + (size_t)(m + 8) * N + n) = make_float2(v10, v11);
            } else {
                uint32_t pk = pack_f16(v00, v01);
                float2 r = unpack_f16(pk);
                *(uint32_t*)(Ch + (size_t)m * N + n) = pk;
                *(uint32_t*)(Cl + (size_t)m * N + n) = pack_f16(v00 - r.x, v01 - r.y);
                pk = pack_f16(v10, v11);
                r = unpack_f16(pk);
                *(uint32_t*)(Ch + (size_t)(m + 8) * N + n) = pk;
                *(uint32_t*)(Cl + (size_t)(m + 8) * N + n) = pack_f16(v10 - r.x, v11 - r.y);
            }
        }
    }
}

// ---------------------------------------------------------------------------
// Flash attention, fp16x2 (Q split hi/lo; K,V single fp16), causal.
// CTA: 128 q-rows x 64-kv chunks. 8 warps x 16 q-rows. (unchanged from R6)
// ---------------------------------------------------------------------------
#define KV_TILE_B 16384                     // 64 rows x 256 B
#define KV_STAGE_B (2 * KV_TILE_B)          // Kh, Vh
#define Q_TILE_B   32768                    // 128 rows x 256 B
#define ATTN_SMEM (2 * Q_TILE_B + 2 * KV_STAGE_B)   // 131072

__global__ __launch_bounds__(256) void attn_mma_kernel()
{
    extern __shared__ char sm8[];
    const uint32_t sb  = smem_u32(sm8);
    const uint32_t sQh = sb, sQl = sb + Q_TILE_B;
    const uint32_t sKV = sb + 2 * Q_TILE_B;

    const int t   = threadIdx.x;
    const int wid = t >> 5;
    const int lid = t & 31;
    const int qt  = blockIdx.x;
    const int h   = blockIdx.y;
    const int b   = blockIdx.z;
    const int m0  = qt * 128;
    const int wm  = wid * 16;
    const int gid = lid >> 2;
    const int tig = lid & 3;
    const int lrow8 = (lid & 7) + ((lid >> 3) & 1) * 8;
    const int lk    = (lid >> 4) & 1;

    const size_t tok0 = ((size_t)b * Sdim + m0) * QKV_N;
    const __half* qh = g_qkvh + tok0 + h * Ddim;
    const __half* ql = g_qkvl + tok0 + h * Ddim;
    const size_t kvtok = (size_t)b * Sdim * QKV_N;
    const __half* kv_base[2] = {
        g_qkvh + kvtok + Cdim + h * Ddim,      // Kh
        g_qkvh + kvtok + 2 * Cdim + h * Ddim   // Vh
    };

    auto load_kv = [&](int stage, int n0) {
        uint32_t dstb = sKV + stage * KV_STAGE_B;
#pragma unroll
        for (int i = 0; i < 8; ++i) {
            int idx  = t + i * 256;            // 0..2047
            int tile = idx >> 10;
            int rem  = idx & 1023;
            int row  = rem >> 4, j = rem & 15;
            const void* src = kv_base[tile] + (size_t)(n0 + row) * QKV_N + j * 8;
            uint32_t dst = dstb + tile * KV_TILE_B + row * 256 + ((j ^ (row & 7)) << 4);
            CP_ASYNC16(dst, src);
        }
    };

    // Q tile loads (group 0, with chunk 0)
#pragma unroll
    for (int i = 0; i < 16; ++i) {
        int idx  = t + i * 256;                // 0..4095
        int tile = idx >> 11;                  // 0: Qh, 1: Ql
        int rem  = idx & 2047;
        int row  = rem >> 4, j = rem & 15;
        const __half* src = (tile == 0 ? qh : ql) + (size_t)row * QKV_N + j * 8;
        uint32_t dst = (tile == 0 ? sQh : sQl) + row * 256 + ((j ^ (row & 7)) << 4);
        CP_ASYNC16(dst, src);
    }
    load_kv(0, 0);
    CP_COMMIT();
    const int ktmax = (m0 >> 6) + 1;
    if (ktmax >= 1) load_kv(1, 64);
    CP_COMMIT();

    float o[16][4];
    float m_i[2] = {-1e30f, -1e30f};
    float l_i[2] = {0.f, 0.f};
#pragma unroll
    for (int nt = 0; nt < 16; ++nt)
#pragma unroll
        for (int e = 0; e < 4; ++e) o[nt][e] = 0.f;

    const float scale = 0.08838834764831845f;   // 1/sqrt(128)
    const int r0g = m0 + wm + gid;

    for (int kt = 0; kt <= ktmax; ++kt) {
        const int n0 = kt << 6;
        CP_WAIT(1);
        __syncthreads();

        const uint32_t st  = sKV + (kt & 1) * KV_STAGE_B;
        const uint32_t sKh = st, sVh = st + KV_TILE_B;

        if (m0 + wm + 15 >= n0) {
            // ---- S = (Qh+Ql) Kh^T ----
            float s[8][4];
#pragma unroll
            for (int nt = 0; nt < 8; ++nt)
#pragma unroll
                for (int e = 0; e < 4; ++e) s[nt][e] = 0.f;

#pragma unroll
            for (int ks = 0; ks < 8; ++ks) {
                const int jg = ks * 2 + lk;
                const int arow = wm + lrow8;
                uint32_t aoff = arow * 256 + ((jg ^ (arow & 7)) << 4);
                uint32_t qfh[4], qfl[4];
                ldsm4(qfh, sQh + aoff);
                ldsm4(qfl, sQl + aoff);
#pragma unroll
                for (int g = 0; g < 4; ++g) {
                    const int brow = g * 16 + lrow8;
                    uint32_t boff = brow * 256 + ((jg ^ (brow & 7)) << 4);
                    uint32_t kh[4];
                    ldsm4(kh, sKh + boff);
                    mma16816(s[2 * g],     qfh, kh[0], kh[2]);
                    mma16816(s[2 * g],     qfl, kh[0], kh[2]);
                    mma16816(s[2 * g + 1], qfh, kh[1], kh[3]);
                    mma16816(s[2 * g + 1], qfl, kh[1], kh[3]);
                }
            }

            // scale + causal mask
            const bool diag = (n0 + 63 > m0 + wm);
#pragma unroll
            for (int nt = 0; nt < 8; ++nt) {
                const int c0 = n0 + nt * 8 + tig * 2;
#pragma unroll
                for (int e = 0; e < 4; ++e) s[nt][e] *= scale;
                if (diag) {
                    if (c0     > r0g)     s[nt][0] = -1e30f;
                    if (c0 + 1 > r0g)     s[nt][1] = -1e30f;
                    if (c0     > r0g + 8) s[nt][2] = -1e30f;
                    if (c0 + 1 > r0g + 8) s[nt][3] = -1e30f;
                }
            }

            // ---- online softmax ----
#pragma unroll
            for (int rr = 0; rr < 2; ++rr) {
                float mx = -1e30f;
#pragma unroll
                for (int nt = 0; nt < 8; ++nt)
                    mx = fmaxf(mx, fmaxf(s[nt][2 * rr], s[nt][2 * rr + 1]));
                mx = fmaxf(mx, __shfl_xor_sync(0xffffffffu, mx, 1));
                mx = fmaxf(mx, __shfl_xor_sync(0xffffffffu, mx, 2));
                float m_new = fmaxf(m_i[rr], mx);
                float alpha = __expf(m_i[rr] - m_new);
                float sum = 0.f;
#pragma unroll
                for (int nt = 0; nt < 8; ++nt) {
                    float p0 = __expf(s[nt][2 * rr]     - m_new);
                    float p1 = __expf(s[nt][2 * rr + 1] - m_new);
                    s[nt][2 * rr]     = p0;
                    s[nt][2 * rr + 1] = p1;
                    sum += p0 + p1;
                }
                sum += __shfl_xor_sync(0xffffffffu, sum, 1);
                sum += __shfl_xor_sync(0xffffffffu, sum, 2);
                l_i[rr] = l_i[rr] * alpha + sum;
                m_i[rr] = m_new;
#pragma unroll
                for (int nt = 0; nt < 16; ++nt) {
                    o[nt][2 * rr]     *= alpha;
                    o[nt][2 * rr + 1] *= alpha;
                }
            }

            // ---- O += (Ph+Pl) Vh ----
#pragma unroll
            for (int j = 0; j < 4; ++j) {
                uint32_t ah[4], al[4];
#pragma unroll
                for (int half = 0; half < 2; ++half) {
                    const float* sp = s[2 * j + half];
#pragma unroll
                    for (int rr = 0; rr < 2; ++rr) {
                        float p0 = sp[2 * rr], p1 = sp[2 * rr + 1];
                        uint32_t pk = pack_f16(p0, p1);
                        float2 r = unpack_f16(pk);
                        ah[half * 2 + rr] = pk;
                        al[half * 2 + rr] = pack_f16(p0 - r.x, p1 - r.y);
                    }
                }
                const int vrow = j * 16 + lrow8;
#pragma unroll
                for (int g = 0; g < 8; ++g) {
                    const int jj = g * 2 + lk;
                    uint32_t voff = vrow * 256 + ((jj ^ (vrow & 7)) << 4);
                    uint32_t vh[4];
                    ldsm4t(vh, sVh + voff);
                    mma16816(o[2 * g],     ah, vh[0], vh[1]);
                    mma16816(o[2 * g],     al, vh[0], vh[1]);
                    mma16816(o[2 * g + 1], ah, vh[2], vh[3]);
                    mma16816(o[2 * g + 1], al, vh[2], vh[3]);
                }
            }
        }

        __syncthreads();
        if (kt + 2 <= ktmax) load_kv(kt & 1, (kt + 2) << 6);
        CP_COMMIT();
    }

    // ---- epilogue: normalize, split to fp16 h/l, write ----
    const float inv0 = 1.0f / l_i[0];
    const float inv1 = 1.0f / l_i[1];
    const size_t ybase = (size_t)b * Sdim * Cdim + (size_t)h * Ddim;
    __half* yh = g_yh + ybase;
    __half* yl = g_yl + ybase;
    const size_t row0 = (size_t)(m0 + wm + gid) * Cdim;
    const size_t row1 = row0 + 8 * Cdim;
#pragma unroll
    for (int nt = 0; nt < 16; ++nt) {
        const int col = nt * 8 + tig * 2;
        float p0 = o[nt][0] * inv0, p1 = o[nt][1] * inv0;
        uint32_t pk = pack_f16(p0, p1);
        float2 r = unpack_f16(pk);
        *(uint32_t*)(yh + row0 + col) = pk;
        *(uint32_t*)(yl + row0 + col) = pack_f16(p0 - r.x, p1 - r.y);
        p0 = o[nt][2] * inv1; p1 = o[nt][3] * inv1;
        pk = pack_f16(p0, p1);
        r = unpack_f16(pk);
        *(uint32_t*)(yh + row1 + col) = pk;
        *(uint32_t*)(yl + row1 + col) = pack_f16(p0 - r.x, p1 - r.y);
    }
}

// ---------------------------------------------------------------------------
// Launch
// ---------------------------------------------------------------------------
extern "C" void kernel_launch(void* const* d_in, const int* in_sizes, int n_in,
                              void* d_out, int out_size)
{
    const float* x      = (const float*)d_in[0];
    const float* w_qkv  = (const float*)d_in[1];
    const float* b_qkv  = (const float*)d_in[2];
    const float* w_proj = (const float*)d_in[3];
    const float* b_proj = (const float*)d_in[4];
    float* out = (float*)d_out;

    __half *qkvh, *qkvl, *xh, *xl, *yh, *yl, *wq, *wp;
    cudaGetSymbolAddress((void**)&qkvh, g_qkvh);
    cudaGetSymbolAddress((void**)&qkvl, g_qkvl);
    cudaGetSymbolAddress((void**)&xh,  g_xh);
    cudaGetSymbolAddress((void**)&xl,  g_xl);
    cudaGetSymbolAddress((void**)&yh,  g_yh);
    cudaGetSymbolAddress((void**)&yl,  g_yl);
    cudaGetSymbolAddress((void**)&wq,  g_wqkvT);
    cudaGetSymbolAddress((void**)&wp,  g_wprojT);

    cudaFuncSetAttribute(gemm_mma_kernel<0>,
                         cudaFuncAttributeMaxDynamicSharedMemorySize, GEMM_SMEM);
    cudaFuncSetAttribute(gemm_mma_kernel<1>,
                         cudaFuncAttributeMaxDynamicSharedMemorySize, GEMM_SMEM);
    cudaFuncSetAttribute(attn_mma_kernel,
                         cudaFuncAttributeMaxDynamicSharedMemorySize, ATTN_SMEM);

    // 1) input splits / weight transposes (fp16)
    {
        int n = Mtok * Cdim;
        split_kernel<<<(n / 4 + 255) / 256, 256>>>(x, xh, xl, n);
    }
    transpose_h_kernel<<<dim3(QKV_N / 32, Cdim / 32), dim3(32, 8)>>>(
        w_qkv, wq, Cdim, QKV_N);
    transpose_h_kernel<<<dim3(Cdim / 32, Cdim / 32), dim3(32, 8)>>>(
        w_proj, wp, Cdim, Cdim);

    // 2) qkv = x @ w_qkv + b_qkv   [8192, 6144] -> split fp16 h/l
    gemm_mma_kernel<1><<<dim3(QKV_N / 128, Mtok / 128), 256, GEMM_SMEM>>>(
        xh, xl, wq, b_qkv, nullptr, qkvh, qkvl, Mtok, QKV_N, Cdim);

    // 3) flash attention -> yh/yl fp16
    {
        dim3 grid(Sdim / 128, Hdim, Bdim);
        attn_mma_kernel<<<grid, 256, ATTN_SMEM>>>();
    }

    // 4) out = y @ w_proj + b_proj   [8192, 2048] fp32
    gemm_mma_kernel<0><<<dim3(Cdim / 128, Mtok / 128), 256, GEMM_SMEM>>>(
        yh, yl, wp, b_proj, out, nullptr, nullptr, Mtok, Cdim, Cdim);
}